// round 1
// baseline (speedup 1.0000x reference)
#include <cuda_runtime.h>
#include <cuda_bf16.h>
#include <cstdint>
#include <cstdio>

// Problem constants
#define B_ 8
#define T_ 1024
#define S_ 1024
#define C_ 1024
#define H_ 16
#define D_ 64

// Scratch buffers (device globals — no allocation allowed)
__device__ float g_q[(size_t)B_ * T_ * C_];        // 32 MB
__device__ float g_kv[(size_t)B_ * S_ * 2 * C_];   // 64 MB
__device__ float g_attn[(size_t)B_ * T_ * C_];     // 32 MB

// ---------------------------------------------------------------------------
// GEMM: C[m,n] = sum_k A[m,k] * B[n,k] + bias[n]
// A: (M,K) row-major, B: (N,K) row-major, C: (M,N) row-major.
// M,N multiples of 128; K multiple of 16. 128x128 tile, BK=16, 256 threads,
// 8x8 microtile per thread.
// ---------------------------------------------------------------------------
__global__ __launch_bounds__(256) void gemm_bias_kernel(
    const float* __restrict__ A, const float* __restrict__ Bm,
    const float* __restrict__ bias, float* __restrict__ C,
    int M, int N, int K)
{
    __shared__ float As[16][128];
    __shared__ float Bs[16][128];

    const int bm = blockIdx.y * 128;
    const int bn = blockIdx.x * 128;
    const int tid = threadIdx.x;

    const int tm = (tid >> 4) << 3;   // 0..120 step 8
    const int tn = (tid & 15) << 3;   // 0..120 step 8

    float acc[8][8];
#pragma unroll
    for (int i = 0; i < 8; i++)
#pragma unroll
        for (int j = 0; j < 8; j++) acc[i][j] = 0.f;

    for (int k0 = 0; k0 < K; k0 += 16) {
#pragma unroll
        for (int it = 0; it < 2; it++) {
            int idx = tid + it * 256;        // 0..511
            int row = idx >> 2;              // 0..127
            int c4  = (idx & 3) * 4;         // 0,4,8,12
            float4 a4 = *(const float4*)(A + (size_t)(bm + row) * K + k0 + c4);
            As[c4 + 0][row] = a4.x; As[c4 + 1][row] = a4.y;
            As[c4 + 2][row] = a4.z; As[c4 + 3][row] = a4.w;
            float4 b4 = *(const float4*)(Bm + (size_t)(bn + row) * K + k0 + c4);
            Bs[c4 + 0][row] = b4.x; Bs[c4 + 1][row] = b4.y;
            Bs[c4 + 2][row] = b4.z; Bs[c4 + 3][row] = b4.w;
        }
        __syncthreads();
#pragma unroll
        for (int kk = 0; kk < 16; kk++) {
            float a[8], b[8];
#pragma unroll
            for (int i = 0; i < 8; i++) a[i] = As[kk][tm + i];
#pragma unroll
            for (int j = 0; j < 8; j++) b[j] = Bs[kk][tn + j];
#pragma unroll
            for (int i = 0; i < 8; i++)
#pragma unroll
                for (int j = 0; j < 8; j++) acc[i][j] += a[i] * b[j];
        }
        __syncthreads();
    }

    // epilogue: add bias, vectorized stores
#pragma unroll
    for (int i = 0; i < 8; i++) {
        float* crow = C + (size_t)(bm + tm + i) * N + bn + tn;
        const float* brow = bias + bn + tn;
#pragma unroll
        for (int j4 = 0; j4 < 8; j4 += 4) {
            float4 v;
            v.x = acc[i][j4 + 0] + brow[j4 + 0];
            v.y = acc[i][j4 + 1] + brow[j4 + 1];
            v.z = acc[i][j4 + 2] + brow[j4 + 2];
            v.w = acc[i][j4 + 3] + brow[j4 + 3];
            *(float4*)(crow + j4) = v;
        }
    }
}

// ---------------------------------------------------------------------------
// Flash attention, causal, d=64. One block = (b, h, 64-query tile).
// 256 threads as 16x16 grid of 4x4 microtiles. Online softmax.
// Dynamic smem: Q(64x65) K(64x65) V(64x64) P(64x65) floats = 66304 B.
// ---------------------------------------------------------------------------
#define QOFF 0
#define KOFF (64 * 65)
#define VOFF (2 * 64 * 65)
#define POFF (2 * 64 * 65 + 64 * 64)
#define FLASH_SMEM_FLOATS (3 * 64 * 65 + 64 * 64)
#define FLASH_SMEM_BYTES (FLASH_SMEM_FLOATS * 4)

__global__ __launch_bounds__(256) void flash_kernel(
    const float* __restrict__ q, const float* __restrict__ kv,
    float* __restrict__ out)
{
    extern __shared__ float sm[];
    const int qt = blockIdx.x;   // 0..15  query tile
    const int h  = blockIdx.y;   // 0..15
    const int b  = blockIdx.z;   // 0..7
    const int tid = threadIdx.x;
    const int r0 = (tid >> 4) * 4;   // row base in 64
    const int c0 = (tid & 15) * 4;   // col base in 64

    // load Q tile (64 x 64)
    const float* qbase = q + (size_t)(b * T_ + qt * 64) * C_ + h * D_;
#pragma unroll
    for (int it = 0; it < 4; it++) {
        int idx = tid + it * 256;         // 0..1023
        int row = idx >> 4;
        int col = (idx & 15) * 4;
        float4 v4 = *(const float4*)(qbase + (size_t)row * C_ + col);
        sm[QOFF + row * 65 + col + 0] = v4.x;
        sm[QOFF + row * 65 + col + 1] = v4.y;
        sm[QOFF + row * 65 + col + 2] = v4.z;
        sm[QOFF + row * 65 + col + 3] = v4.w;
    }

    float m[4], l[4], o[4][4];
#pragma unroll
    for (int i = 0; i < 4; i++) {
        m[i] = -1e30f; l[i] = 0.f;
#pragma unroll
        for (int j = 0; j < 4; j++) o[i][j] = 0.f;
    }
    const float scale = 0.125f;  // 1/sqrt(64)

    for (int st = 0; st <= qt; st++) {
        __syncthreads();   // protect K/V/P from previous iteration readers
        const float* kbase = kv + (size_t)(b * S_ + st * 64) * (2 * C_) + h * D_;
        const float* vbase = kbase + C_;
#pragma unroll
        for (int it = 0; it < 4; it++) {
            int idx = tid + it * 256;
            int row = idx >> 4;
            int col = (idx & 15) * 4;
            float4 k4 = *(const float4*)(kbase + (size_t)row * (2 * C_) + col);
            sm[KOFF + row * 65 + col + 0] = k4.x;
            sm[KOFF + row * 65 + col + 1] = k4.y;
            sm[KOFF + row * 65 + col + 2] = k4.z;
            sm[KOFF + row * 65 + col + 3] = k4.w;
            float4 v4 = *(const float4*)(vbase + (size_t)row * (2 * C_) + col);
            sm[VOFF + row * 64 + col + 0] = v4.x;
            sm[VOFF + row * 64 + col + 1] = v4.y;
            sm[VOFF + row * 64 + col + 2] = v4.z;
            sm[VOFF + row * 64 + col + 3] = v4.w;
        }
        __syncthreads();

        // scores 4x4
        float s[4][4];
#pragma unroll
        for (int i = 0; i < 4; i++)
#pragma unroll
            for (int j = 0; j < 4; j++) s[i][j] = 0.f;
#pragma unroll 16
        for (int kk = 0; kk < 64; kk++) {
            float a[4], bb[4];
#pragma unroll
            for (int i = 0; i < 4; i++) a[i] = sm[QOFF + (r0 + i) * 65 + kk];
#pragma unroll
            for (int j = 0; j < 4; j++) bb[j] = sm[KOFF + (c0 + j) * 65 + kk];
#pragma unroll
            for (int i = 0; i < 4; i++)
#pragma unroll
                for (int j = 0; j < 4; j++) s[i][j] += a[i] * bb[j];
        }

        const bool diag = (st == qt);
#pragma unroll
        for (int i = 0; i < 4; i++)
#pragma unroll
            for (int j = 0; j < 4; j++) {
                s[i][j] *= scale;
                if (diag && (c0 + j > r0 + i)) s[i][j] = -1e30f;
            }

        // online softmax per row (16 lanes per row-group via shfl width 16)
#pragma unroll
        for (int i = 0; i < 4; i++) {
            float mt = s[i][0];
#pragma unroll
            for (int j = 1; j < 4; j++) mt = fmaxf(mt, s[i][j]);
#pragma unroll
            for (int off = 8; off >= 1; off >>= 1)
                mt = fmaxf(mt, __shfl_xor_sync(0xffffffffu, mt, off, 16));
            float mn = fmaxf(m[i], mt);
            float corr = __expf(m[i] - mn);
            m[i] = mn;
            float rs = 0.f;
            float p[4];
#pragma unroll
            for (int j = 0; j < 4; j++) { p[j] = __expf(s[i][j] - mn); rs += p[j]; }
#pragma unroll
            for (int off = 8; off >= 1; off >>= 1)
                rs += __shfl_xor_sync(0xffffffffu, rs, off, 16);
            l[i] = l[i] * corr + rs;
#pragma unroll
            for (int j = 0; j < 4; j++) {
                o[i][j] *= corr;
                sm[POFF + (r0 + i) * 65 + c0 + j] = p[j];
            }
        }
        __syncthreads();

        // o += P @ V
#pragma unroll 16
        for (int ss = 0; ss < 64; ss++) {
            float pv[4], vv[4];
#pragma unroll
            for (int i = 0; i < 4; i++) pv[i] = sm[POFF + (r0 + i) * 65 + ss];
#pragma unroll
            for (int j = 0; j < 4; j++) vv[j] = sm[VOFF + ss * 64 + c0 + j];
#pragma unroll
            for (int i = 0; i < 4; i++)
#pragma unroll
                for (int j = 0; j < 4; j++) o[i][j] += pv[i] * vv[j];
        }
    }

    // finalize: divide by l, write [B,T,C] layout
#pragma unroll
    for (int i = 0; i < 4; i++) {
        float inv = 1.f / l[i];
        float* orow = out + (size_t)(b * T_ + qt * 64 + r0 + i) * C_ + h * D_ + c0;
        float4 v;
        v.x = o[i][0] * inv; v.y = o[i][1] * inv;
        v.z = o[i][2] * inv; v.w = o[i][3] * inv;
        *(float4*)orow = v;
    }
}

// ---------------------------------------------------------------------------
// Launch
// ---------------------------------------------------------------------------
extern "C" void kernel_launch(void* const* d_in, const int* in_sizes, int n_in,
                              void* d_out, int out_size)
{
    const float* x       = (const float*)d_in[0];   // (B,T,C)
    const float* feature = (const float*)d_in[1];   // (B,S,C)
    const float* Wc      = (const float*)d_in[2];   // (C,C)
    const float* bc      = (const float*)d_in[3];   // (C)
    const float* Wf      = (const float*)d_in[4];   // (2C,C)
    const float* bf      = (const float*)d_in[5];   // (2C)
    const float* Wp      = (const float*)d_in[6];   // (C,C)
    const float* bp      = (const float*)d_in[7];   // (C)
    float* out           = (float*)d_out;           // (B,T,C)

    float *qb, *kvb, *attnb;
    cudaGetSymbolAddress((void**)&qb, g_q);
    cudaGetSymbolAddress((void**)&kvb, g_kv);
    cudaGetSymbolAddress((void**)&attnb, g_attn);

    // 1) q = x @ Wc^T + bc        : M=8192, N=1024, K=1024
    {
        dim3 grid(C_ / 128, (B_ * T_) / 128);
        gemm_bias_kernel<<<grid, 256>>>(x, Wc, bc, qb, B_ * T_, C_, C_);
    }
    // 2) kv = feature @ Wf^T + bf : M=8192, N=2048, K=1024
    {
        dim3 grid((2 * C_) / 128, (B_ * S_) / 128);
        gemm_bias_kernel<<<grid, 256>>>(feature, Wf, bf, kvb, B_ * S_, 2 * C_, C_);
    }
    // 3) flash attention (causal)
    {
        static bool attr_set = false;
        // setting the attribute is idempotent and deterministic; do it every call
        cudaFuncSetAttribute(flash_kernel,
                             cudaFuncAttributeMaxDynamicSharedMemorySize,
                             FLASH_SMEM_BYTES);
        (void)attr_set;
        dim3 grid(T_ / 64, H_, B_);
        flash_kernel<<<grid, 256, FLASH_SMEM_BYTES>>>(qb, kvb, attnb);
    }
    // 4) out = attn @ Wp^T + bp   : M=8192, N=1024, K=1024
    {
        dim3 grid(C_ / 128, (B_ * T_) / 128);
        gemm_bias_kernel<<<grid, 256>>>(attnb, Wp, bp, out, B_ * T_, C_, C_);
    }
}

// round 3
// speedup vs baseline: 1.8893x; 1.8893x over previous
#include <cuda_runtime.h>
#include <cuda_bf16.h>
#include <cstdint>

// Problem constants
#define B_ 8
#define T_ 1024
#define S_ 1024
#define C_ 1024
#define H_ 16
#define D_ 64

// Scratch buffers (device globals — no allocation allowed)
__device__ float g_q[(size_t)B_ * T_ * C_];        // 32 MB
__device__ float g_kv[(size_t)B_ * S_ * 2 * C_];   // 64 MB
__device__ float g_attn[(size_t)B_ * T_ * C_];     // 32 MB

__device__ __forceinline__ uint32_t smem_to_u32(const void* p) {
    uint32_t a;
    asm("{ .reg .u64 t; cvta.to.shared.u64 t, %1; cvt.u32.u64 %0, t; }"
        : "=r"(a) : "l"(p));
    return a;
}

#define LDSM_X4(r0, r1, r2, r3, addr) \
    asm volatile("ldmatrix.sync.aligned.m8n8.x4.shared.b16 {%0,%1,%2,%3}, [%4];" \
                 : "=r"(r0), "=r"(r1), "=r"(r2), "=r"(r3) : "r"(addr))

#define MMA_BF16(d, a, b) \
    asm volatile("mma.sync.aligned.m16n8k16.row.col.f32.bf16.bf16.f32 " \
                 "{%0,%1,%2,%3}, {%4,%5,%6,%7}, {%8,%9}, {%0,%1,%2,%3};" \
                 : "+f"((d)[0]), "+f"((d)[1]), "+f"((d)[2]), "+f"((d)[3]) \
                 : "r"((a)[0]), "r"((a)[1]), "r"((a)[2]), "r"((a)[3]), \
                   "r"((b)[0]), "r"((b)[1]))

// ===========================================================================
// mma.sync GEMM: C[m,n] = sum_k A[m,k]*B[n,k] + bias[n]
// fp32 via bf16 hi/lo split (3 MMAs). 128x128 tile/CTA, BK=32, 8 warps (4x2),
// warp tile 32x64. Smem row stride 40 bf16 (80B) -> conflict-free ldmatrix.
// ===========================================================================
#define RSTRIDE 40
#define AHI_E 0
#define ALO_E (128 * RSTRIDE)
#define BHI_E (2 * 128 * RSTRIDE)
#define BLO_E (3 * 128 * RSTRIDE)
#define GEMM_SMEM_E (4 * 128 * RSTRIDE)   // 20480 bf16 = 40KB

__global__ __launch_bounds__(256, 2) void gemm_mma_kernel(
    const float* __restrict__ A, const float* __restrict__ Bm,
    const float* __restrict__ bias, float* __restrict__ C,
    int M, int N, int K)
{
    __shared__ __nv_bfloat16 sm[GEMM_SMEM_E];
    const int tid = threadIdx.x;
    const int lane = tid & 31;
    const int wid = tid >> 5;
    const int bm = blockIdx.y * 128;
    const int bn = blockIdx.x * 128;
    const int wm = (wid & 3) * 32;    // warp row offset within tile
    const int wn = (wid >> 2) * 64;   // warp col offset within tile

    const uint32_t sbase = smem_to_u32(sm);

    float acc[2][8][4];
#pragma unroll
    for (int mi = 0; mi < 2; mi++)
#pragma unroll
        for (int nj = 0; nj < 8; nj++)
#pragma unroll
            for (int e = 0; e < 4; e++) acc[mi][nj][e] = 0.f;

    // ldmatrix lane-address components (elements)
    const int a_row_l = lane & 15;           // row within 16
    const int a_col_l = (lane >> 4) * 8;     // k-block select
    const int b_seg = lane >> 3;             // 0..3
    const int b_r8 = lane & 7;
    const int b_row_add = (b_seg >> 1) * 8;  // +8 rows for matrices 2,3
    const int b_col_add = (b_seg & 1) * 8;   // +8 cols for matrices 1,3

    for (int k0 = 0; k0 < K; k0 += 32) {
        __syncthreads();   // protect smem from previous iteration readers
        // ---- load & convert A,B chunk (128x32 each) to hi/lo bf16 smem ----
#pragma unroll
        for (int it = 0; it < 4; it++) {
            int idx = tid + it * 256;        // 0..1023
            int row = idx >> 3;              // 0..127
            int c4 = (idx & 7) << 2;         // 0..28 step 4
            int eo = row * RSTRIDE + c4;

            float4 a4 = *(const float4*)(A + (size_t)(bm + row) * K + k0 + c4);
            {
                __nv_bfloat162 h01, h23, l01, l23;
                __nv_bfloat16 h;
                h = __float2bfloat16(a4.x); h01.x = h;
                l01.x = __float2bfloat16(a4.x - __bfloat162float(h));
                h = __float2bfloat16(a4.y); h01.y = h;
                l01.y = __float2bfloat16(a4.y - __bfloat162float(h));
                h = __float2bfloat16(a4.z); h23.x = h;
                l23.x = __float2bfloat16(a4.z - __bfloat162float(h));
                h = __float2bfloat16(a4.w); h23.y = h;
                l23.y = __float2bfloat16(a4.w - __bfloat162float(h));
                *(__nv_bfloat162*)(sm + AHI_E + eo)     = h01;
                *(__nv_bfloat162*)(sm + AHI_E + eo + 2) = h23;
                *(__nv_bfloat162*)(sm + ALO_E + eo)     = l01;
                *(__nv_bfloat162*)(sm + ALO_E + eo + 2) = l23;
            }
            float4 b4 = *(const float4*)(Bm + (size_t)(bn + row) * K + k0 + c4);
            {
                __nv_bfloat162 h01, h23, l01, l23;
                __nv_bfloat16 h;
                h = __float2bfloat16(b4.x); h01.x = h;
                l01.x = __float2bfloat16(b4.x - __bfloat162float(h));
                h = __float2bfloat16(b4.y); h01.y = h;
                l01.y = __float2bfloat16(b4.y - __bfloat162float(h));
                h = __float2bfloat16(b4.z); h23.x = h;
                l23.x = __float2bfloat16(b4.z - __bfloat162float(h));
                h = __float2bfloat16(b4.w); h23.y = h;
                l23.y = __float2bfloat16(b4.w - __bfloat162float(h));
                *(__nv_bfloat162*)(sm + BHI_E + eo)     = h01;
                *(__nv_bfloat162*)(sm + BHI_E + eo + 2) = h23;
                *(__nv_bfloat162*)(sm + BLO_E + eo)     = l01;
                *(__nv_bfloat162*)(sm + BLO_E + eo + 2) = l23;
            }
        }
        __syncthreads();

        // ---- compute: 2 k-steps of 16 ----
#pragma unroll
        for (int ks = 0; ks < 2; ks++) {
            const int kcol = ks * 16 + a_col_l;
            // A fragments (hi and lo), 2 m-frags
            uint32_t ah[2][4], al[2][4];
#pragma unroll
            for (int mi = 0; mi < 2; mi++) {
                int eo = (wm + mi * 16 + a_row_l) * RSTRIDE + kcol;
                LDSM_X4(ah[mi][0], ah[mi][1], ah[mi][2], ah[mi][3],
                        sbase + 2 * (AHI_E + eo));
                LDSM_X4(al[mi][0], al[mi][1], al[mi][2], al[mi][3],
                        sbase + 2 * (ALO_E + eo));
            }
            // B fragments in groups of 2 n-frags (one x4), consumed immediately
#pragma unroll
            for (int g = 0; g < 4; g++) {
                int brow = wn + g * 16 + b_row_add + b_r8;
                int bcol = ks * 16 + b_col_add;
                int eo = brow * RSTRIDE + bcol;
                uint32_t bh[4], bl[4];
                LDSM_X4(bh[0], bh[1], bh[2], bh[3], sbase + 2 * (BHI_E + eo));
                LDSM_X4(bl[0], bl[1], bl[2], bl[3], sbase + 2 * (BLO_E + eo));
#pragma unroll
                for (int half = 0; half < 2; half++) {
                    int nj = g * 2 + half;
                    uint32_t* bhp = bh + half * 2;
                    uint32_t* blp = bl + half * 2;
#pragma unroll
                    for (int mi = 0; mi < 2; mi++) {
                        MMA_BF16(acc[mi][nj], ah[mi], bhp);
                        MMA_BF16(acc[mi][nj], ah[mi], blp);
                        MMA_BF16(acc[mi][nj], al[mi], bhp);
                    }
                }
            }
        }
    }

    // ---- epilogue: fragment-mapped stores + bias ----
    const int er = lane >> 2;
    const int ec = (lane & 3) * 2;
#pragma unroll
    for (int mi = 0; mi < 2; mi++) {
#pragma unroll
        for (int nj = 0; nj < 8; nj++) {
            int m0 = bm + wm + mi * 16 + er;
            int n0 = bn + wn + nj * 8 + ec;
            float b0 = __ldg(bias + n0);
            float b1 = __ldg(bias + n0 + 1);
            float2 v0 = make_float2(acc[mi][nj][0] + b0, acc[mi][nj][1] + b1);
            float2 v1 = make_float2(acc[mi][nj][2] + b0, acc[mi][nj][3] + b1);
            *(float2*)(C + (size_t)m0 * N + n0) = v0;
            *(float2*)(C + (size_t)(m0 + 8) * N + n0) = v1;
        }
    }
}

// ---------------------------------------------------------------------------
// Flash attention, causal, d=64 (fp32 SIMT, unchanged this round)
// ---------------------------------------------------------------------------
#define QOFF 0
#define KOFF (64 * 65)
#define VOFF (2 * 64 * 65)
#define POFF (2 * 64 * 65 + 64 * 64)
#define FLASH_SMEM_FLOATS (3 * 64 * 65 + 64 * 64)
#define FLASH_SMEM_BYTES (FLASH_SMEM_FLOATS * 4)

__global__ __launch_bounds__(256) void flash_kernel(
    const float* __restrict__ q, const float* __restrict__ kv,
    float* __restrict__ out)
{
    extern __shared__ float sm[];
    const int qt = blockIdx.x;
    const int h  = blockIdx.y;
    const int b  = blockIdx.z;
    const int tid = threadIdx.x;
    const int r0 = (tid >> 4) * 4;
    const int c0 = (tid & 15) * 4;

    const float* qbase = q + (size_t)(b * T_ + qt * 64) * C_ + h * D_;
#pragma unroll
    for (int it = 0; it < 4; it++) {
        int idx = tid + it * 256;
        int row = idx >> 4;
        int col = (idx & 15) * 4;
        float4 v4 = *(const float4*)(qbase + (size_t)row * C_ + col);
        sm[QOFF + row * 65 + col + 0] = v4.x;
        sm[QOFF + row * 65 + col + 1] = v4.y;
        sm[QOFF + row * 65 + col + 2] = v4.z;
        sm[QOFF + row * 65 + col + 3] = v4.w;
    }

    float m[4], l[4], o[4][4];
#pragma unroll
    for (int i = 0; i < 4; i++) {
        m[i] = -1e30f; l[i] = 0.f;
#pragma unroll
        for (int j = 0; j < 4; j++) o[i][j] = 0.f;
    }
    const float scale = 0.125f;

    for (int st = 0; st <= qt; st++) {
        __syncthreads();
        const float* kbase = kv + (size_t)(b * S_ + st * 64) * (2 * C_) + h * D_;
        const float* vbase = kbase + C_;
#pragma unroll
        for (int it = 0; it < 4; it++) {
            int idx = tid + it * 256;
            int row = idx >> 4;
            int col = (idx & 15) * 4;
            float4 k4 = *(const float4*)(kbase + (size_t)row * (2 * C_) + col);
            sm[KOFF + row * 65 + col + 0] = k4.x;
            sm[KOFF + row * 65 + col + 1] = k4.y;
            sm[KOFF + row * 65 + col + 2] = k4.z;
            sm[KOFF + row * 65 + col + 3] = k4.w;
            float4 v4 = *(const float4*)(vbase + (size_t)row * (2 * C_) + col);
            sm[VOFF + row * 64 + col + 0] = v4.x;
            sm[VOFF + row * 64 + col + 1] = v4.y;
            sm[VOFF + row * 64 + col + 2] = v4.z;
            sm[VOFF + row * 64 + col + 3] = v4.w;
        }
        __syncthreads();

        float s[4][4];
#pragma unroll
        for (int i = 0; i < 4; i++)
#pragma unroll
            for (int j = 0; j < 4; j++) s[i][j] = 0.f;
#pragma unroll 16
        for (int kk = 0; kk < 64; kk++) {
            float a[4], bb[4];
#pragma unroll
            for (int i = 0; i < 4; i++) a[i] = sm[QOFF + (r0 + i) * 65 + kk];
#pragma unroll
            for (int j = 0; j < 4; j++) bb[j] = sm[KOFF + (c0 + j) * 65 + kk];
#pragma unroll
            for (int i = 0; i < 4; i++)
#pragma unroll
                for (int j = 0; j < 4; j++) s[i][j] += a[i] * bb[j];
        }

        const bool diag = (st == qt);
#pragma unroll
        for (int i = 0; i < 4; i++)
#pragma unroll
            for (int j = 0; j < 4; j++) {
                s[i][j] *= scale;
                if (diag && (c0 + j > r0 + i)) s[i][j] = -1e30f;
            }

#pragma unroll
        for (int i = 0; i < 4; i++) {
            float mt = s[i][0];
#pragma unroll
            for (int j = 1; j < 4; j++) mt = fmaxf(mt, s[i][j]);
#pragma unroll
            for (int off = 8; off >= 1; off >>= 1)
                mt = fmaxf(mt, __shfl_xor_sync(0xffffffffu, mt, off, 16));
            float mn = fmaxf(m[i], mt);
            float corr = __expf(m[i] - mn);
            m[i] = mn;
            float rs = 0.f;
            float p[4];
#pragma unroll
            for (int j = 0; j < 4; j++) { p[j] = __expf(s[i][j] - mn); rs += p[j]; }
#pragma unroll
            for (int off = 8; off >= 1; off >>= 1)
                rs += __shfl_xor_sync(0xffffffffu, rs, off, 16);
            l[i] = l[i] * corr + rs;
#pragma unroll
            for (int j = 0; j < 4; j++) {
                o[i][j] *= corr;
                sm[POFF + (r0 + i) * 65 + c0 + j] = p[j];
            }
        }
        __syncthreads();

#pragma unroll 16
        for (int ss = 0; ss < 64; ss++) {
            float pv[4], vv[4];
#pragma unroll
            for (int i = 0; i < 4; i++) pv[i] = sm[POFF + (r0 + i) * 65 + ss];
#pragma unroll
            for (int j = 0; j < 4; j++) vv[j] = sm[VOFF + ss * 64 + c0 + j];
#pragma unroll
            for (int i = 0; i < 4; i++)
#pragma unroll
                for (int j = 0; j < 4; j++) o[i][j] += pv[i] * vv[j];
        }
    }

#pragma unroll
    for (int i = 0; i < 4; i++) {
        float inv = 1.f / l[i];
        float* orow = out + (size_t)(b * T_ + qt * 64 + r0 + i) * C_ + h * D_ + c0;
        float4 v;
        v.x = o[i][0] * inv; v.y = o[i][1] * inv;
        v.z = o[i][2] * inv; v.w = o[i][3] * inv;
        *(float4*)orow = v;
    }
}

// ---------------------------------------------------------------------------
// Launch
// ---------------------------------------------------------------------------
extern "C" void kernel_launch(void* const* d_in, const int* in_sizes, int n_in,
                              void* d_out, int out_size)
{
    const float* x       = (const float*)d_in[0];
    const float* feature = (const float*)d_in[1];
    const float* Wc      = (const float*)d_in[2];
    const float* bc      = (const float*)d_in[3];
    const float* Wf      = (const float*)d_in[4];
    const float* bf      = (const float*)d_in[5];
    const float* Wp      = (const float*)d_in[6];
    const float* bp      = (const float*)d_in[7];
    float* out           = (float*)d_out;

    float *qb, *kvb, *attnb;
    cudaGetSymbolAddress((void**)&qb, g_q);
    cudaGetSymbolAddress((void**)&kvb, g_kv);
    cudaGetSymbolAddress((void**)&attnb, g_attn);

    cudaFuncSetAttribute(flash_kernel,
                         cudaFuncAttributeMaxDynamicSharedMemorySize, FLASH_SMEM_BYTES);

    // 1) q = x @ Wc^T + bc        : M=8192, N=1024, K=1024
    {
        dim3 grid(C_ / 128, (B_ * T_) / 128);
        gemm_mma_kernel<<<grid, 256>>>(x, Wc, bc, qb, B_ * T_, C_, C_);
    }
    // 2) kv = feature @ Wf^T + bf : M=8192, N=2048, K=1024
    {
        dim3 grid((2 * C_) / 128, (B_ * S_) / 128);
        gemm_mma_kernel<<<grid, 256>>>(feature, Wf, bf, kvb, B_ * S_, 2 * C_, C_);
    }
    // 3) flash attention (causal)
    {
        dim3 grid(T_ / 64, H_, B_);
        flash_kernel<<<grid, 256, FLASH_SMEM_BYTES>>>(qb, kvb, attnb);
    }
    // 4) out = attn @ Wp^T + bp   : M=8192, N=1024, K=1024
    {
        dim3 grid(C_ / 128, (B_ * T_) / 128);
        gemm_mma_kernel<<<grid, 256>>>(attnb, Wp, bp, out, B_ * T_, C_, C_);
    }
}

// round 4
// speedup vs baseline: 1.9040x; 1.0078x over previous
#include <cuda_runtime.h>
#include <cuda_bf16.h>
#include <cstdint>

// Problem constants
#define B_ 8
#define T_ 1024
#define S_ 1024
#define C_ 1024
#define H_ 16
#define D_ 64

// Scratch buffers (device globals — no allocation allowed)
__device__ float g_q[(size_t)B_ * T_ * C_];        // 32 MB
__device__ float g_kv[(size_t)B_ * S_ * 2 * C_];   // 64 MB
__device__ float g_attn[(size_t)B_ * T_ * C_];     // 32 MB

__device__ __forceinline__ uint32_t smem_to_u32(const void* p) {
    uint32_t a;
    asm("{ .reg .u64 t; cvta.to.shared.u64 t, %1; cvt.u32.u64 %0, t; }"
        : "=r"(a) : "l"(p));
    return a;
}

#define LDSM_X4(r0, r1, r2, r3, addr) \
    asm volatile("ldmatrix.sync.aligned.m8n8.x4.shared.b16 {%0,%1,%2,%3}, [%4];" \
                 : "=r"(r0), "=r"(r1), "=r"(r2), "=r"(r3) : "r"(addr))

#define MMA_BF16(d, a, b) \
    asm volatile("mma.sync.aligned.m16n8k16.row.col.f32.bf16.bf16.f32 " \
                 "{%0,%1,%2,%3}, {%4,%5,%6,%7}, {%8,%9}, {%0,%1,%2,%3};" \
                 : "+f"((d)[0]), "+f"((d)[1]), "+f"((d)[2]), "+f"((d)[3]) \
                 : "r"((a)[0]), "r"((a)[1]), "r"((a)[2]), "r"((a)[3]), \
                   "r"((b)[0]), "r"((b)[1]))

// ===========================================================================
// mma.sync GEMM: C[m,n] = sum_k A[m,k]*B[n,k] + bias[n]
// fp32 via bf16 hi/lo split (3 MMAs). 128x128 tile/CTA, BK=32, 8 warps (4x2),
// warp tile 32x64. Smem row stride 40 bf16 (80B) -> conflict-free ldmatrix.
// ===========================================================================
#define RSTRIDE 40
#define AHI_E 0
#define ALO_E (128 * RSTRIDE)
#define BHI_E (2 * 128 * RSTRIDE)
#define BLO_E (3 * 128 * RSTRIDE)
#define GEMM_SMEM_E (4 * 128 * RSTRIDE)   // 20480 bf16 = 40KB

__global__ __launch_bounds__(256, 2) void gemm_mma_kernel(
    const float* __restrict__ A, const float* __restrict__ Bm,
    const float* __restrict__ bias, float* __restrict__ C,
    int M, int N, int K)
{
    __shared__ __nv_bfloat16 sm[GEMM_SMEM_E];
    const int tid = threadIdx.x;
    const int lane = tid & 31;
    const int wid = tid >> 5;
    const int bm = blockIdx.y * 128;
    const int bn = blockIdx.x * 128;
    const int wm = (wid & 3) * 32;    // warp row offset within tile
    const int wn = (wid >> 2) * 64;   // warp col offset within tile

    const uint32_t sbase = smem_to_u32(sm);

    float acc[2][8][4];
#pragma unroll
    for (int mi = 0; mi < 2; mi++)
#pragma unroll
        for (int nj = 0; nj < 8; nj++)
#pragma unroll
            for (int e = 0; e < 4; e++) acc[mi][nj][e] = 0.f;

    // ldmatrix lane-address components (elements)
    const int a_row_l = lane & 15;           // row within 16
    const int a_col_l = (lane >> 4) * 8;     // k-block select
    const int b_seg = lane >> 3;             // 0..3
    const int b_r8 = lane & 7;
    const int b_row_add = (b_seg >> 1) * 8;  // +8 rows for matrices 2,3
    const int b_col_add = (b_seg & 1) * 8;   // +8 cols for matrices 1,3

    for (int k0 = 0; k0 < K; k0 += 32) {
        __syncthreads();   // protect smem from previous iteration readers
        // ---- load & convert A,B chunk (128x32 each) to hi/lo bf16 smem ----
#pragma unroll
        for (int it = 0; it < 4; it++) {
            int idx = tid + it * 256;        // 0..1023
            int row = idx >> 3;              // 0..127
            int c4 = (idx & 7) << 2;         // 0..28 step 4
            int eo = row * RSTRIDE + c4;

            float4 a4 = *(const float4*)(A + (size_t)(bm + row) * K + k0 + c4);
            {
                __nv_bfloat162 h01, h23, l01, l23;
                __nv_bfloat16 h;
                h = __float2bfloat16(a4.x); h01.x = h;
                l01.x = __float2bfloat16(a4.x - __bfloat162float(h));
                h = __float2bfloat16(a4.y); h01.y = h;
                l01.y = __float2bfloat16(a4.y - __bfloat162float(h));
                h = __float2bfloat16(a4.z); h23.x = h;
                l23.x = __float2bfloat16(a4.z - __bfloat162float(h));
                h = __float2bfloat16(a4.w); h23.y = h;
                l23.y = __float2bfloat16(a4.w - __bfloat162float(h));
                *(__nv_bfloat162*)(sm + AHI_E + eo)     = h01;
                *(__nv_bfloat162*)(sm + AHI_E + eo + 2) = h23;
                *(__nv_bfloat162*)(sm + ALO_E + eo)     = l01;
                *(__nv_bfloat162*)(sm + ALO_E + eo + 2) = l23;
            }
            float4 b4 = *(const float4*)(Bm + (size_t)(bn + row) * K + k0 + c4);
            {
                __nv_bfloat162 h01, h23, l01, l23;
                __nv_bfloat16 h;
                h = __float2bfloat16(b4.x); h01.x = h;
                l01.x = __float2bfloat16(b4.x - __bfloat162float(h));
                h = __float2bfloat16(b4.y); h01.y = h;
                l01.y = __float2bfloat16(b4.y - __bfloat162float(h));
                h = __float2bfloat16(b4.z); h23.x = h;
                l23.x = __float2bfloat16(b4.z - __bfloat162float(h));
                h = __float2bfloat16(b4.w); h23.y = h;
                l23.y = __float2bfloat16(b4.w - __bfloat162float(h));
                *(__nv_bfloat162*)(sm + BHI_E + eo)     = h01;
                *(__nv_bfloat162*)(sm + BHI_E + eo + 2) = h23;
                *(__nv_bfloat162*)(sm + BLO_E + eo)     = l01;
                *(__nv_bfloat162*)(sm + BLO_E + eo + 2) = l23;
            }
        }
        __syncthreads();

        // ---- compute: 2 k-steps of 16 ----
#pragma unroll
        for (int ks = 0; ks < 2; ks++) {
            const int kcol = ks * 16 + a_col_l;
            // A fragments (hi and lo), 2 m-frags
            uint32_t ah[2][4], al[2][4];
#pragma unroll
            for (int mi = 0; mi < 2; mi++) {
                int eo = (wm + mi * 16 + a_row_l) * RSTRIDE + kcol;
                LDSM_X4(ah[mi][0], ah[mi][1], ah[mi][2], ah[mi][3],
                        sbase + 2 * (AHI_E + eo));
                LDSM_X4(al[mi][0], al[mi][1], al[mi][2], al[mi][3],
                        sbase + 2 * (ALO_E + eo));
            }
            // B fragments in groups of 2 n-frags (one x4), consumed immediately
#pragma unroll
            for (int g = 0; g < 4; g++) {
                int brow = wn + g * 16 + b_row_add + b_r8;
                int bcol = ks * 16 + b_col_add;
                int eo = brow * RSTRIDE + bcol;
                uint32_t bh[4], bl[4];
                LDSM_X4(bh[0], bh[1], bh[2], bh[3], sbase + 2 * (BHI_E + eo));
                LDSM_X4(bl[0], bl[1], bl[2], bl[3], sbase + 2 * (BLO_E + eo));
#pragma unroll
                for (int half = 0; half < 2; half++) {
                    int nj = g * 2 + half;
                    uint32_t* bhp = bh + half * 2;
                    uint32_t* blp = bl + half * 2;
#pragma unroll
                    for (int mi = 0; mi < 2; mi++) {
                        MMA_BF16(acc[mi][nj], ah[mi], bhp);
                        MMA_BF16(acc[mi][nj], ah[mi], blp);
                        MMA_BF16(acc[mi][nj], al[mi], bhp);
                    }
                }
            }
        }
    }

    // ---- epilogue: fragment-mapped stores + bias ----
    const int er = lane >> 2;
    const int ec = (lane & 3) * 2;
#pragma unroll
    for (int mi = 0; mi < 2; mi++) {
#pragma unroll
        for (int nj = 0; nj < 8; nj++) {
            int m0 = bm + wm + mi * 16 + er;
            int n0 = bn + wn + nj * 8 + ec;
            float b0 = __ldg(bias + n0);
            float b1 = __ldg(bias + n0 + 1);
            float2 v0 = make_float2(acc[mi][nj][0] + b0, acc[mi][nj][1] + b1);
            float2 v1 = make_float2(acc[mi][nj][2] + b0, acc[mi][nj][3] + b1);
            *(float2*)(C + (size_t)m0 * N + n0) = v0;
            *(float2*)(C + (size_t)(m0 + 8) * N + n0) = v1;
        }
    }
}

// ---------------------------------------------------------------------------
// Flash attention, causal, d=64 (fp32 SIMT, unchanged this round)
// ---------------------------------------------------------------------------
#define QOFF 0
#define KOFF (64 * 65)
#define VOFF (2 * 64 * 65)
#define POFF (2 * 64 * 65 + 64 * 64)
#define FLASH_SMEM_FLOATS (3 * 64 * 65 + 64 * 64)
#define FLASH_SMEM_BYTES (FLASH_SMEM_FLOATS * 4)

__global__ __launch_bounds__(256) void flash_kernel(
    const float* __restrict__ q, const float* __restrict__ kv,
    float* __restrict__ out)
{
    extern __shared__ float sm[];
    const int qt = blockIdx.x;
    const int h  = blockIdx.y;
    const int b  = blockIdx.z;
    const int tid = threadIdx.x;
    const int r0 = (tid >> 4) * 4;
    const int c0 = (tid & 15) * 4;

    const float* qbase = q + (size_t)(b * T_ + qt * 64) * C_ + h * D_;
#pragma unroll
    for (int it = 0; it < 4; it++) {
        int idx = tid + it * 256;
        int row = idx >> 4;
        int col = (idx & 15) * 4;
        float4 v4 = *(const float4*)(qbase + (size_t)row * C_ + col);
        sm[QOFF + row * 65 + col + 0] = v4.x;
        sm[QOFF + row * 65 + col + 1] = v4.y;
        sm[QOFF + row * 65 + col + 2] = v4.z;
        sm[QOFF + row * 65 + col + 3] = v4.w;
    }

    float m[4], l[4], o[4][4];
#pragma unroll
    for (int i = 0; i < 4; i++) {
        m[i] = -1e30f; l[i] = 0.f;
#pragma unroll
        for (int j = 0; j < 4; j++) o[i][j] = 0.f;
    }
    const float scale = 0.125f;

    for (int st = 0; st <= qt; st++) {
        __syncthreads();
        const float* kbase = kv + (size_t)(b * S_ + st * 64) * (2 * C_) + h * D_;
        const float* vbase = kbase + C_;
#pragma unroll
        for (int it = 0; it < 4; it++) {
            int idx = tid + it * 256;
            int row = idx >> 4;
            int col = (idx & 15) * 4;
            float4 k4 = *(const float4*)(kbase + (size_t)row * (2 * C_) + col);
            sm[KOFF + row * 65 + col + 0] = k4.x;
            sm[KOFF + row * 65 + col + 1] = k4.y;
            sm[KOFF + row * 65 + col + 2] = k4.z;
            sm[KOFF + row * 65 + col + 3] = k4.w;
            float4 v4 = *(const float4*)(vbase + (size_t)row * (2 * C_) + col);
            sm[VOFF + row * 64 + col + 0] = v4.x;
            sm[VOFF + row * 64 + col + 1] = v4.y;
            sm[VOFF + row * 64 + col + 2] = v4.z;
            sm[VOFF + row * 64 + col + 3] = v4.w;
        }
        __syncthreads();

        float s[4][4];
#pragma unroll
        for (int i = 0; i < 4; i++)
#pragma unroll
            for (int j = 0; j < 4; j++) s[i][j] = 0.f;
#pragma unroll 16
        for (int kk = 0; kk < 64; kk++) {
            float a[4], bb[4];
#pragma unroll
            for (int i = 0; i < 4; i++) a[i] = sm[QOFF + (r0 + i) * 65 + kk];
#pragma unroll
            for (int j = 0; j < 4; j++) bb[j] = sm[KOFF + (c0 + j) * 65 + kk];
#pragma unroll
            for (int i = 0; i < 4; i++)
#pragma unroll
                for (int j = 0; j < 4; j++) s[i][j] += a[i] * bb[j];
        }

        const bool diag = (st == qt);
#pragma unroll
        for (int i = 0; i < 4; i++)
#pragma unroll
            for (int j = 0; j < 4; j++) {
                s[i][j] *= scale;
                if (diag && (c0 + j > r0 + i)) s[i][j] = -1e30f;
            }

#pragma unroll
        for (int i = 0; i < 4; i++) {
            float mt = s[i][0];
#pragma unroll
            for (int j = 1; j < 4; j++) mt = fmaxf(mt, s[i][j]);
#pragma unroll
            for (int off = 8; off >= 1; off >>= 1)
                mt = fmaxf(mt, __shfl_xor_sync(0xffffffffu, mt, off, 16));
            float mn = fmaxf(m[i], mt);
            float corr = __expf(m[i] - mn);
            m[i] = mn;
            float rs = 0.f;
            float p[4];
#pragma unroll
            for (int j = 0; j < 4; j++) { p[j] = __expf(s[i][j] - mn); rs += p[j]; }
#pragma unroll
            for (int off = 8; off >= 1; off >>= 1)
                rs += __shfl_xor_sync(0xffffffffu, rs, off, 16);
            l[i] = l[i] * corr + rs;
#pragma unroll
            for (int j = 0; j < 4; j++) {
                o[i][j] *= corr;
                sm[POFF + (r0 + i) * 65 + c0 + j] = p[j];
            }
        }
        __syncthreads();

#pragma unroll 16
        for (int ss = 0; ss < 64; ss++) {
            float pv[4], vv[4];
#pragma unroll
            for (int i = 0; i < 4; i++) pv[i] = sm[POFF + (r0 + i) * 65 + ss];
#pragma unroll
            for (int j = 0; j < 4; j++) vv[j] = sm[VOFF + ss * 64 + c0 + j];
#pragma unroll
            for (int i = 0; i < 4; i++)
#pragma unroll
                for (int j = 0; j < 4; j++) o[i][j] += pv[i] * vv[j];
        }
    }

#pragma unroll
    for (int i = 0; i < 4; i++) {
        float inv = 1.f / l[i];
        float* orow = out + (size_t)(b * T_ + qt * 64 + r0 + i) * C_ + h * D_ + c0;
        float4 v;
        v.x = o[i][0] * inv; v.y = o[i][1] * inv;
        v.z = o[i][2] * inv; v.w = o[i][3] * inv;
        *(float4*)orow = v;
    }
}

// ---------------------------------------------------------------------------
// Launch
// ---------------------------------------------------------------------------
extern "C" void kernel_launch(void* const* d_in, const int* in_sizes, int n_in,
                              void* d_out, int out_size)
{
    const float* x       = (const float*)d_in[0];
    const float* feature = (const float*)d_in[1];
    const float* Wc      = (const float*)d_in[2];
    const float* bc      = (const float*)d_in[3];
    const float* Wf      = (const float*)d_in[4];
    const float* bf      = (const float*)d_in[5];
    const float* Wp      = (const float*)d_in[6];
    const float* bp      = (const float*)d_in[7];
    float* out           = (float*)d_out;

    float *qb, *kvb, *attnb;
    cudaGetSymbolAddress((void**)&qb, g_q);
    cudaGetSymbolAddress((void**)&kvb, g_kv);
    cudaGetSymbolAddress((void**)&attnb, g_attn);

    cudaFuncSetAttribute(flash_kernel,
                         cudaFuncAttributeMaxDynamicSharedMemorySize, FLASH_SMEM_BYTES);

    // 1) q = x @ Wc^T + bc        : M=8192, N=1024, K=1024
    {
        dim3 grid(C_ / 128, (B_ * T_) / 128);
        gemm_mma_kernel<<<grid, 256>>>(x, Wc, bc, qb, B_ * T_, C_, C_);
    }
    // 2) kv = feature @ Wf^T + bf : M=8192, N=2048, K=1024
    {
        dim3 grid((2 * C_) / 128, (B_ * S_) / 128);
        gemm_mma_kernel<<<grid, 256>>>(feature, Wf, bf, kvb, B_ * S_, 2 * C_, C_);
    }
    // 3) flash attention (causal)
    {
        dim3 grid(T_ / 64, H_, B_);
        flash_kernel<<<grid, 256, FLASH_SMEM_BYTES>>>(qb, kvb, attnb);
    }
    // 4) out = attn @ Wp^T + bp   : M=8192, N=1024, K=1024
    {
        dim3 grid(C_ / 128, (B_ * T_) / 128);
        gemm_mma_kernel<<<grid, 256>>>(attnb, Wp, bp, out, B_ * T_, C_, C_);
    }
}

// round 5
// speedup vs baseline: 2.4404x; 1.2817x over previous
#include <cuda_runtime.h>
#include <cuda_bf16.h>
#include <cstdint>

// Problem constants
#define B_ 8
#define T_ 1024
#define S_ 1024
#define C_ 1024
#define H_ 16
#define D_ 64

#define NX   ((size_t)B_ * T_ * C_)        // 8M
#define NKV  ((size_t)B_ * S_ * 2 * C_)    // 16M

// bf16 hi/lo scratch (device globals — no allocation allowed)
__device__ __nv_bfloat16 g_xh[NX],  g_xl[NX];
__device__ __nv_bfloat16 g_fh[NX],  g_fl[NX];
__device__ __nv_bfloat16 g_Wch[(size_t)C_ * C_],     g_Wcl[(size_t)C_ * C_];
__device__ __nv_bfloat16 g_Wfh[(size_t)2 * C_ * C_], g_Wfl[(size_t)2 * C_ * C_];
__device__ __nv_bfloat16 g_Wph[(size_t)C_ * C_],     g_Wpl[(size_t)C_ * C_];
__device__ __nv_bfloat16 g_qh[NX],  g_ql[NX];
__device__ __nv_bfloat16 g_kvh[NKV], g_kvl[NKV];
__device__ __nv_bfloat16 g_ah[NX],  g_al[NX];

__device__ __forceinline__ uint32_t smem_to_u32(const void* p) {
    uint32_t a;
    asm("{ .reg .u64 t; cvta.to.shared.u64 t, %1; cvt.u32.u64 %0, t; }"
        : "=r"(a) : "l"(p));
    return a;
}

#define LDSM_X4(r0, r1, r2, r3, addr) \
    asm volatile("ldmatrix.sync.aligned.m8n8.x4.shared.b16 {%0,%1,%2,%3}, [%4];" \
                 : "=r"(r0), "=r"(r1), "=r"(r2), "=r"(r3) : "r"(addr))

#define LDSM_X4_T(r0, r1, r2, r3, addr) \
    asm volatile("ldmatrix.sync.aligned.m8n8.x4.trans.shared.b16 {%0,%1,%2,%3}, [%4];" \
                 : "=r"(r0), "=r"(r1), "=r"(r2), "=r"(r3) : "r"(addr))

#define MMA_BF16(d, a, b) \
    asm volatile("mma.sync.aligned.m16n8k16.row.col.f32.bf16.bf16.f32 " \
                 "{%0,%1,%2,%3}, {%4,%5,%6,%7}, {%8,%9}, {%0,%1,%2,%3};" \
                 : "+f"((d)[0]), "+f"((d)[1]), "+f"((d)[2]), "+f"((d)[3]) \
                 : "r"((a)[0]), "r"((a)[1]), "r"((a)[2]), "r"((a)[3]), \
                   "r"((b)[0]), "r"((b)[1]))

#define CP_ASYNC16(dst, src) \
    asm volatile("cp.async.cg.shared.global [%0], [%1], 16;" :: "r"(dst), "l"(src))
#define CP_COMMIT() asm volatile("cp.async.commit_group;")
#define CP_WAIT1()  asm volatile("cp.async.wait_group 1;" ::: "memory")

__device__ __forceinline__ uint32_t pack2bf(float a, float b) {
    __nv_bfloat162 t = __floats2bfloat162_rn(a, b);   // .x = a (low), .y = b
    return *(uint32_t*)&t;
}

// ===========================================================================
// Split kernel: fp32 -> bf16 hi + bf16 lo (elementwise, vectorized)
// ===========================================================================
__global__ __launch_bounds__(256) void split_kernel(
    const float* __restrict__ src, __nv_bfloat16* __restrict__ h,
    __nv_bfloat16* __restrict__ l, int n4)
{
    int i = blockIdx.x * 256 + threadIdx.x;
    if (i >= n4) return;
    float4 v = *(const float4*)(src + (size_t)i * 4);
    __nv_bfloat16 h0 = __float2bfloat16(v.x), h1 = __float2bfloat16(v.y);
    __nv_bfloat16 h2 = __float2bfloat16(v.z), h3 = __float2bfloat16(v.w);
    __nv_bfloat162 hh0; hh0.x = h0; hh0.y = h1;
    __nv_bfloat162 hh1; hh1.x = h2; hh1.y = h3;
    __nv_bfloat162 ll0;
    ll0.x = __float2bfloat16(v.x - __bfloat162float(h0));
    ll0.y = __float2bfloat16(v.y - __bfloat162float(h1));
    __nv_bfloat162 ll1;
    ll1.x = __float2bfloat16(v.z - __bfloat162float(h2));
    ll1.y = __float2bfloat16(v.w - __bfloat162float(h3));
    *(__nv_bfloat162*)(h + (size_t)i * 4)     = hh0;
    *(__nv_bfloat162*)(h + (size_t)i * 4 + 2) = hh1;
    *(__nv_bfloat162*)(l + (size_t)i * 4)     = ll0;
    *(__nv_bfloat162*)(l + (size_t)i * 4 + 2) = ll1;
}

// ===========================================================================
// Pipelined mma.sync GEMM on preconverted bf16 hi/lo inputs.
// C[m,n] = sum_k A[m,k]*B[n,k] + bias[n]; 3 MMAs per product (hi/lo split).
// 128x128 tile/CTA, BK=32, 2-stage cp.async pipeline, 8 warps (4x2).
// Output: fp32 (Cf) or bf16 hi/lo (Ch/Cl).
// ===========================================================================
#define RSTRIDE 40
#define TILE_E  (128 * RSTRIDE)                 // 5120 elements / tile
#define STAGE_E (4 * TILE_E)                    // AH, AL, BH, BL
#define GEMM_SMEM_BYTES (2 * STAGE_E * 2)       // 81920 bytes

__global__ __launch_bounds__(256, 2) void gemm_mma_kernel(
    const __nv_bfloat16* __restrict__ Ah, const __nv_bfloat16* __restrict__ Al,
    const __nv_bfloat16* __restrict__ Bh, const __nv_bfloat16* __restrict__ Bl,
    const float* __restrict__ bias,
    float* __restrict__ Cf, __nv_bfloat16* __restrict__ Ch,
    __nv_bfloat16* __restrict__ Cl,
    int M, int N, int K)
{
    extern __shared__ __nv_bfloat16 sm[];
    const int tid = threadIdx.x;
    const int lane = tid & 31;
    const int wid = tid >> 5;
    const int bm = blockIdx.y * 128;
    const int bn = blockIdx.x * 128;
    const int wm = (wid & 3) * 32;
    const int wn = (wid >> 2) * 64;
    const uint32_t sbase = smem_to_u32(sm);

    const __nv_bfloat16* srcs[4] = {
        Ah + (size_t)bm * K, Al + (size_t)bm * K,
        Bh + (size_t)bn * K, Bl + (size_t)bn * K };

    // loader mapping: idx 0..511 per tile -> row = idx>>2, chunk = idx&3 (8 el)
    const int ld_row = tid >> 1;            // 0..127  (256 threads, 2 chunks each)
    const int ld_ch0 = (tid & 1) * 2;       // chunks {0,1} or {2,3}

    float acc[2][8][4];
#pragma unroll
    for (int mi = 0; mi < 2; mi++)
#pragma unroll
        for (int nj = 0; nj < 8; nj++)
#pragma unroll
            for (int e = 0; e < 4; e++) acc[mi][nj][e] = 0.f;

    const int a_row_l = lane & 15;
    const int a_col_l = (lane >> 4) * 8;
    const int b_seg = lane >> 3;
    const int b_r8 = lane & 7;
    const int b_row_add = (b_seg >> 1) * 8;
    const int b_col_add = (b_seg & 1) * 8;

    const int nchunk = K >> 5;

    // --- prologue: load stage 0 ---
#pragma unroll
    for (int t = 0; t < 4; t++) {
#pragma unroll
        for (int c = 0; c < 2; c++) {
            uint32_t sdst = sbase +
                (uint32_t)(t * TILE_E + ld_row * RSTRIDE + (ld_ch0 + c) * 8) * 2;
            const __nv_bfloat16* gsrc = srcs[t] + (size_t)ld_row * K + (ld_ch0 + c) * 8;
            CP_ASYNC16(sdst, gsrc);
        }
    }
    CP_COMMIT();

    for (int ck = 0; ck < nchunk; ck++) {
        // issue loads for next chunk into other stage
        if (ck + 1 < nchunk) {
            const uint32_t stoff = (uint32_t)(((ck + 1) & 1) * STAGE_E) * 2;
            const int k0n = (ck + 1) << 5;
#pragma unroll
            for (int t = 0; t < 4; t++) {
#pragma unroll
                for (int c = 0; c < 2; c++) {
                    uint32_t sdst = sbase + stoff +
                        (uint32_t)(t * TILE_E + ld_row * RSTRIDE + (ld_ch0 + c) * 8) * 2;
                    const __nv_bfloat16* gsrc =
                        srcs[t] + (size_t)ld_row * K + k0n + (ld_ch0 + c) * 8;
                    CP_ASYNC16(sdst, gsrc);
                }
            }
        }
        CP_COMMIT();
        CP_WAIT1();
        __syncthreads();

        const uint32_t st = sbase + (uint32_t)((ck & 1) * STAGE_E) * 2;
        const uint32_t sAH = st;
        const uint32_t sAL = st + (uint32_t)TILE_E * 2;
        const uint32_t sBH = st + (uint32_t)(2 * TILE_E) * 2;
        const uint32_t sBL = st + (uint32_t)(3 * TILE_E) * 2;

#pragma unroll
        for (int ks = 0; ks < 2; ks++) {
            const int kcol = ks * 16 + a_col_l;
            uint32_t ah[2][4], al[2][4];
#pragma unroll
            for (int mi = 0; mi < 2; mi++) {
                uint32_t eo = (uint32_t)((wm + mi * 16 + a_row_l) * RSTRIDE + kcol) * 2;
                LDSM_X4(ah[mi][0], ah[mi][1], ah[mi][2], ah[mi][3], sAH + eo);
                LDSM_X4(al[mi][0], al[mi][1], al[mi][2], al[mi][3], sAL + eo);
            }
#pragma unroll
            for (int g = 0; g < 4; g++) {
                uint32_t eo = (uint32_t)((wn + g * 16 + b_row_add + b_r8) * RSTRIDE +
                                         ks * 16 + b_col_add) * 2;
                uint32_t bh[4], bl[4];
                LDSM_X4(bh[0], bh[1], bh[2], bh[3], sBH + eo);
                LDSM_X4(bl[0], bl[1], bl[2], bl[3], sBL + eo);
#pragma unroll
                for (int half = 0; half < 2; half++) {
                    int nj = g * 2 + half;
                    uint32_t* bhp = bh + half * 2;
                    uint32_t* blp = bl + half * 2;
#pragma unroll
                    for (int mi = 0; mi < 2; mi++) {
                        MMA_BF16(acc[mi][nj], ah[mi], bhp);
                        MMA_BF16(acc[mi][nj], ah[mi], blp);
                        MMA_BF16(acc[mi][nj], al[mi], bhp);
                    }
                }
            }
        }
        __syncthreads();
    }

    // ---- epilogue ----
    const int er = lane >> 2;
    const int ec = (lane & 3) * 2;
#pragma unroll
    for (int mi = 0; mi < 2; mi++) {
#pragma unroll
        for (int nj = 0; nj < 8; nj++) {
            int m0 = bm + wm + mi * 16 + er;
            int n0 = bn + wn + nj * 8 + ec;
            float b0 = __ldg(bias + n0);
            float b1 = __ldg(bias + n0 + 1);
            float v00 = acc[mi][nj][0] + b0, v01 = acc[mi][nj][1] + b1;
            float v10 = acc[mi][nj][2] + b0, v11 = acc[mi][nj][3] + b1;
            if (Cf) {
                *(float2*)(Cf + (size_t)m0 * N + n0) = make_float2(v00, v01);
                *(float2*)(Cf + (size_t)(m0 + 8) * N + n0) = make_float2(v10, v11);
            } else {
                __nv_bfloat16 h00 = __float2bfloat16(v00);
                __nv_bfloat16 h01 = __float2bfloat16(v01);
                __nv_bfloat16 h10 = __float2bfloat16(v10);
                __nv_bfloat16 h11 = __float2bfloat16(v11);
                __nv_bfloat162 hv0; hv0.x = h00; hv0.y = h01;
                __nv_bfloat162 hv1; hv1.x = h10; hv1.y = h11;
                __nv_bfloat162 lv0;
                lv0.x = __float2bfloat16(v00 - __bfloat162float(h00));
                lv0.y = __float2bfloat16(v01 - __bfloat162float(h01));
                __nv_bfloat162 lv1;
                lv1.x = __float2bfloat16(v10 - __bfloat162float(h10));
                lv1.y = __float2bfloat16(v11 - __bfloat162float(h11));
                *(__nv_bfloat162*)(Ch + (size_t)m0 * N + n0) = hv0;
                *(__nv_bfloat162*)(Ch + (size_t)(m0 + 8) * N + n0) = hv1;
                *(__nv_bfloat162*)(Cl + (size_t)m0 * N + n0) = lv0;
                *(__nv_bfloat162*)(Cl + (size_t)(m0 + 8) * N + n0) = lv1;
            }
        }
    }
}

// ===========================================================================
// Tensor-core flash attention, causal, d=64.
// Block = (qt, h, b), 128 threads (4 warps), warp owns m16 query rows.
// QK^T and PV via m16n8k16 bf16 MMAs with hi/lo split (3 MMAs each).
// V transposed via ldmatrix.trans. Output -> bf16 hi/lo (attn buffers).
// ===========================================================================
#define FSTRIDE 72

__global__ __launch_bounds__(128) void flash_mma_kernel(
    const __nv_bfloat16* __restrict__ qh, const __nv_bfloat16* __restrict__ ql,
    const __nv_bfloat16* __restrict__ kvh, const __nv_bfloat16* __restrict__ kvl,
    __nv_bfloat16* __restrict__ oh, __nv_bfloat16* __restrict__ ol)
{
    __shared__ __nv_bfloat16 skh[64 * FSTRIDE], skl[64 * FSTRIDE];
    __shared__ __nv_bfloat16 svh[64 * FSTRIDE], svl[64 * FSTRIDE];

    const int qt = blockIdx.x, h = blockIdx.y, b = blockIdx.z;
    const int tid = threadIdx.x;
    const int lane = tid & 31;
    const int wid = tid >> 5;
    const int wm = wid * 16;

    const int fr = lane >> 2;          // 0..7
    const int fc = (lane & 3) * 2;     // 0,2,4,6
    const uint32_t skh_b = smem_to_u32(skh);
    const uint32_t skl_b = smem_to_u32(skl);
    const uint32_t svh_b = smem_to_u32(svh);
    const uint32_t svl_b = smem_to_u32(svl);

    // --- Q fragments (hi/lo) for 4 k-steps, loaded from global once ---
    uint32_t qfh[4][4], qfl[4][4];
    {
        const size_t qrow0 = (size_t)(b * T_ + qt * 64 + wm + fr) * C_ + h * D_;
        const size_t qrow8 = qrow0 + (size_t)8 * C_;
#pragma unroll
        for (int ks = 0; ks < 4; ks++) {
            int c0 = ks * 16 + fc;
            qfh[ks][0] = *(const uint32_t*)(qh + qrow0 + c0);
            qfh[ks][1] = *(const uint32_t*)(qh + qrow8 + c0);
            qfh[ks][2] = *(const uint32_t*)(qh + qrow0 + c0 + 8);
            qfh[ks][3] = *(const uint32_t*)(qh + qrow8 + c0 + 8);
            qfl[ks][0] = *(const uint32_t*)(ql + qrow0 + c0);
            qfl[ks][1] = *(const uint32_t*)(ql + qrow8 + c0);
            qfl[ks][2] = *(const uint32_t*)(ql + qrow0 + c0 + 8);
            qfl[ks][3] = *(const uint32_t*)(ql + qrow8 + c0 + 8);
        }
    }

    float mrow0 = -1e30f, mrow1 = -1e30f, lrow0 = 0.f, lrow1 = 0.f;
    float oacc[8][4];
#pragma unroll
    for (int j = 0; j < 8; j++)
#pragma unroll
        for (int e = 0; e < 4; e++) oacc[j][e] = 0.f;

    const int b_seg = lane >> 3;
    const int b_r8 = lane & 7;
    const int b_row_add = (b_seg >> 1) * 8;
    const int b_col_add = (b_seg & 1) * 8;
    // V trans-ldsm lane addressing
    const int v_row_l = lane & 15;
    const int v_col_l = (lane >> 4) * 8;

    const float scale = 0.125f;
    const int row_g0 = qt * 64 + wm + fr;
    const int row_g1 = row_g0 + 8;

    for (int st = 0; st <= qt; st++) {
        __syncthreads();
        // ---- load K,V hi/lo tiles (64 x 64 each) ----
        {
            const size_t kvrow = (size_t)(b * S_ + st * 64) * (2 * C_) + h * D_;
#pragma unroll
            for (int it = 0; it < 4; it++) {
                int idx = tid + it * 128;        // 0..511
                int row = idx >> 3;
                int ch = (idx & 7) * 8;
                size_t g = kvrow + (size_t)row * (2 * C_) + ch;
                int so = row * FSTRIDE + ch;
                *(uint4*)(skh + so) = *(const uint4*)(kvh + g);
                *(uint4*)(skl + so) = *(const uint4*)(kvl + g);
                *(uint4*)(svh + so) = *(const uint4*)(kvh + g + C_);
                *(uint4*)(svl + so) = *(const uint4*)(kvl + g + C_);
            }
        }
        __syncthreads();

        // ---- S = Q K^T (hi/lo, 3 MMAs) ----
        float sacc[8][4];
#pragma unroll
        for (int j = 0; j < 8; j++)
#pragma unroll
            for (int e = 0; e < 4; e++) sacc[j][e] = 0.f;

#pragma unroll
        for (int ks = 0; ks < 4; ks++) {
#pragma unroll
            for (int g = 0; g < 4; g++) {
                uint32_t eo = (uint32_t)((g * 16 + b_row_add + b_r8) * FSTRIDE +
                                         ks * 16 + b_col_add) * 2;
                uint32_t bh[4], bl[4];
                LDSM_X4(bh[0], bh[1], bh[2], bh[3], skh_b + eo);
                LDSM_X4(bl[0], bl[1], bl[2], bl[3], skl_b + eo);
#pragma unroll
                for (int half = 0; half < 2; half++) {
                    int nj = g * 2 + half;
                    uint32_t* bhp = bh + half * 2;
                    uint32_t* blp = bl + half * 2;
                    MMA_BF16(sacc[nj], qfh[ks], bhp);
                    MMA_BF16(sacc[nj], qfh[ks], blp);
                    MMA_BF16(sacc[nj], qfl[ks], bhp);
                }
            }
        }

        // ---- scale + causal mask (diag tile only) ----
        const bool diag = (st == qt);
#pragma unroll
        for (int nj = 0; nj < 8; nj++) {
#pragma unroll
            for (int e = 0; e < 4; e++) {
                float v = sacc[nj][e] * scale;
                if (diag) {
                    int col = st * 64 + nj * 8 + fc + (e & 1);
                    int row = (e < 2) ? row_g0 : row_g1;
                    if (col > row) v = -1e30f;
                }
                sacc[nj][e] = v;
            }
        }

        // ---- online softmax ----
        float mx0 = -1e30f, mx1 = -1e30f;
#pragma unroll
        for (int nj = 0; nj < 8; nj++) {
            mx0 = fmaxf(mx0, fmaxf(sacc[nj][0], sacc[nj][1]));
            mx1 = fmaxf(mx1, fmaxf(sacc[nj][2], sacc[nj][3]));
        }
        mx0 = fmaxf(mx0, __shfl_xor_sync(0xffffffffu, mx0, 1));
        mx0 = fmaxf(mx0, __shfl_xor_sync(0xffffffffu, mx0, 2));
        mx1 = fmaxf(mx1, __shfl_xor_sync(0xffffffffu, mx1, 1));
        mx1 = fmaxf(mx1, __shfl_xor_sync(0xffffffffu, mx1, 2));

        float mn0 = fmaxf(mrow0, mx0);
        float mn1 = fmaxf(mrow1, mx1);
        float c0 = __expf(mrow0 - mn0);
        float c1 = __expf(mrow1 - mn1);
        mrow0 = mn0; mrow1 = mn1;

        float rs0 = 0.f, rs1 = 0.f;
        uint32_t pfh[4][4], pfl[4][4];
#pragma unroll
        for (int kp = 0; kp < 4; kp++) {
            float p[2][4];  // [njsub][e]
#pragma unroll
            for (int s2 = 0; s2 < 2; s2++) {
                int nj = kp * 2 + s2;
                p[s2][0] = __expf(sacc[nj][0] - mn0);
                p[s2][1] = __expf(sacc[nj][1] - mn0);
                p[s2][2] = __expf(sacc[nj][2] - mn1);
                p[s2][3] = __expf(sacc[nj][3] - mn1);
                rs0 += p[s2][0] + p[s2][1];
                rs1 += p[s2][2] + p[s2][3];
            }
            // A-frag packing: a0=(r0,c..c+1) a1=(r1,..) a2=(r0,c+8..) a3=(r1,c+8..)
#pragma unroll
            for (int s2 = 0; s2 < 2; s2++) {
                float h00 = __bfloat162float(__float2bfloat16(p[s2][0]));
                float h01 = __bfloat162float(__float2bfloat16(p[s2][1]));
                float h10 = __bfloat162float(__float2bfloat16(p[s2][2]));
                float h11 = __bfloat162float(__float2bfloat16(p[s2][3]));
                pfh[kp][0 + s2 * 2] = pack2bf(h00, h01);
                pfh[kp][1 + s2 * 2] = pack2bf(h10, h11);
                pfl[kp][0 + s2 * 2] = pack2bf(p[s2][0] - h00, p[s2][1] - h01);
                pfl[kp][1 + s2 * 2] = pack2bf(p[s2][2] - h10, p[s2][3] - h11);
            }
        }
        rs0 += __shfl_xor_sync(0xffffffffu, rs0, 1);
        rs0 += __shfl_xor_sync(0xffffffffu, rs0, 2);
        rs1 += __shfl_xor_sync(0xffffffffu, rs1, 1);
        rs1 += __shfl_xor_sync(0xffffffffu, rs1, 2);
        lrow0 = lrow0 * c0 + rs0;
        lrow1 = lrow1 * c1 + rs1;

#pragma unroll
        for (int j = 0; j < 8; j++) {
            oacc[j][0] *= c0; oacc[j][1] *= c0;
            oacc[j][2] *= c1; oacc[j][3] *= c1;
        }

        // ---- O += P V  (V transposed via ldsm.trans) ----
#pragma unroll
        for (int kp = 0; kp < 4; kp++) {
#pragma unroll
            for (int g = 0; g < 4; g++) {
                uint32_t eo = (uint32_t)((kp * 16 + v_row_l) * FSTRIDE +
                                         g * 16 + v_col_l) * 2;
                uint32_t vh[4], vl[4];
                LDSM_X4_T(vh[0], vh[1], vh[2], vh[3], svh_b + eo);
                LDSM_X4_T(vl[0], vl[1], vl[2], vl[3], svl_b + eo);
#pragma unroll
                for (int half = 0; half < 2; half++) {
                    int njd = g * 2 + half;
                    uint32_t* vhp = vh + half * 2;
                    uint32_t* vlp = vl + half * 2;
                    MMA_BF16(oacc[njd], pfh[kp], vhp);
                    MMA_BF16(oacc[njd], pfh[kp], vlp);
                    MMA_BF16(oacc[njd], pfl[kp], vhp);
                }
            }
        }
    }

    // ---- finalize: divide by l, hi/lo split, store bf16 ----
    const float inv0 = 1.f / lrow0;
    const float inv1 = 1.f / lrow1;
    const size_t orow0 = (size_t)(b * T_ + row_g0) * C_ + h * D_;
    const size_t orow8 = orow0 + (size_t)8 * C_;
#pragma unroll
    for (int njd = 0; njd < 8; njd++) {
        int col = njd * 8 + fc;
        float v00 = oacc[njd][0] * inv0, v01 = oacc[njd][1] * inv0;
        float v10 = oacc[njd][2] * inv1, v11 = oacc[njd][3] * inv1;
        __nv_bfloat16 h00 = __float2bfloat16(v00), h01 = __float2bfloat16(v01);
        __nv_bfloat16 h10 = __float2bfloat16(v10), h11 = __float2bfloat16(v11);
        __nv_bfloat162 hv0; hv0.x = h00; hv0.y = h01;
        __nv_bfloat162 hv1; hv1.x = h10; hv1.y = h11;
        __nv_bfloat162 lv0;
        lv0.x = __float2bfloat16(v00 - __bfloat162float(h00));
        lv0.y = __float2bfloat16(v01 - __bfloat162float(h01));
        __nv_bfloat162 lv1;
        lv1.x = __float2bfloat16(v10 - __bfloat162float(h10));
        lv1.y = __float2bfloat16(v11 - __bfloat162float(h11));
        *(__nv_bfloat162*)(oh + orow0 + col) = hv0;
        *(__nv_bfloat162*)(oh + orow8 + col) = hv1;
        *(__nv_bfloat162*)(ol + orow0 + col) = lv0;
        *(__nv_bfloat162*)(ol + orow8 + col) = lv1;
    }
}

// ---------------------------------------------------------------------------
// Launch
// ---------------------------------------------------------------------------
extern "C" void kernel_launch(void* const* d_in, const int* in_sizes, int n_in,
                              void* d_out, int out_size)
{
    const float* x       = (const float*)d_in[0];
    const float* feature = (const float*)d_in[1];
    const float* Wc      = (const float*)d_in[2];
    const float* bc      = (const float*)d_in[3];
    const float* Wf      = (const float*)d_in[4];
    const float* bf      = (const float*)d_in[5];
    const float* Wp      = (const float*)d_in[6];
    const float* bp      = (const float*)d_in[7];
    float* out           = (float*)d_out;

    __nv_bfloat16 *xh, *xl, *fh, *fl, *Wch, *Wcl, *Wfh, *Wfl, *Wph, *Wpl;
    __nv_bfloat16 *qh, *ql, *kvh, *kvl, *ah, *al;
    cudaGetSymbolAddress((void**)&xh, g_xh);   cudaGetSymbolAddress((void**)&xl, g_xl);
    cudaGetSymbolAddress((void**)&fh, g_fh);   cudaGetSymbolAddress((void**)&fl, g_fl);
    cudaGetSymbolAddress((void**)&Wch, g_Wch); cudaGetSymbolAddress((void**)&Wcl, g_Wcl);
    cudaGetSymbolAddress((void**)&Wfh, g_Wfh); cudaGetSymbolAddress((void**)&Wfl, g_Wfl);
    cudaGetSymbolAddress((void**)&Wph, g_Wph); cudaGetSymbolAddress((void**)&Wpl, g_Wpl);
    cudaGetSymbolAddress((void**)&qh, g_qh);   cudaGetSymbolAddress((void**)&ql, g_ql);
    cudaGetSymbolAddress((void**)&kvh, g_kvh); cudaGetSymbolAddress((void**)&kvl, g_kvl);
    cudaGetSymbolAddress((void**)&ah, g_ah);   cudaGetSymbolAddress((void**)&al, g_al);

    cudaFuncSetAttribute(gemm_mma_kernel,
                         cudaFuncAttributeMaxDynamicSharedMemorySize, GEMM_SMEM_BYTES);

    // ---- 0) split fp32 inputs to bf16 hi/lo ----
    {
        int n4;
        n4 = (int)(NX / 4);
        split_kernel<<<(n4 + 255) / 256, 256>>>(x, xh, xl, n4);
        split_kernel<<<(n4 + 255) / 256, 256>>>(feature, fh, fl, n4);
        n4 = C_ * C_ / 4;
        split_kernel<<<(n4 + 255) / 256, 256>>>(Wc, Wch, Wcl, n4);
        split_kernel<<<(n4 + 255) / 256, 256>>>(Wp, Wph, Wpl, n4);
        n4 = 2 * C_ * C_ / 4;
        split_kernel<<<(n4 + 255) / 256, 256>>>(Wf, Wfh, Wfl, n4);
    }

    // ---- 1) q = x @ Wc^T + bc  -> bf16 hi/lo ----
    {
        dim3 grid(C_ / 128, (B_ * T_) / 128);
        gemm_mma_kernel<<<grid, 256, GEMM_SMEM_BYTES>>>(
            xh, xl, Wch, Wcl, bc, nullptr, qh, ql, B_ * T_, C_, C_);
    }
    // ---- 2) kv = feature @ Wf^T + bf -> bf16 hi/lo ----
    {
        dim3 grid((2 * C_) / 128, (B_ * S_) / 128);
        gemm_mma_kernel<<<grid, 256, GEMM_SMEM_BYTES>>>(
            fh, fl, Wfh, Wfl, bf, nullptr, kvh, kvl, B_ * S_, 2 * C_, C_);
    }
    // ---- 3) flash attention (causal, tensor cores) -> bf16 hi/lo ----
    {
        dim3 grid(T_ / 64, H_, B_);
        flash_mma_kernel<<<grid, 128>>>(qh, ql, kvh, kvl, ah, al);
    }
    // ---- 4) out = attn @ Wp^T + bp -> fp32 ----
    {
        dim3 grid(C_ / 128, (B_ * T_) / 128);
        gemm_mma_kernel<<<grid, 256, GEMM_SMEM_BYTES>>>(
            ah, al, Wph, Wpl, bp, out, nullptr, nullptr, B_ * T_, C_, C_);
    }
}

// round 6
// speedup vs baseline: 2.4482x; 1.0032x over previous
#include <cuda_runtime.h>
#include <cuda_bf16.h>
#include <cstdint>

// Problem constants
#define B_ 8
#define T_ 1024
#define S_ 1024
#define C_ 1024
#define H_ 16
#define D_ 64

#define NX   ((size_t)B_ * T_ * C_)        // 8M
#define NKV  ((size_t)B_ * S_ * 2 * C_)    // 16M

// bf16 hi/lo scratch (device globals — no allocation allowed)
__device__ __nv_bfloat16 g_xh[NX],  g_xl[NX];
__device__ __nv_bfloat16 g_fh[NX],  g_fl[NX];
__device__ __nv_bfloat16 g_Wch[(size_t)C_ * C_],     g_Wcl[(size_t)C_ * C_];
__device__ __nv_bfloat16 g_Wfh[(size_t)2 * C_ * C_], g_Wfl[(size_t)2 * C_ * C_];
__device__ __nv_bfloat16 g_Wph[(size_t)C_ * C_],     g_Wpl[(size_t)C_ * C_];
__device__ __nv_bfloat16 g_qh[NX],  g_ql[NX];
__device__ __nv_bfloat16 g_kvh[NKV], g_kvl[NKV];
__device__ __nv_bfloat16 g_ah[NX],  g_al[NX];

__device__ __forceinline__ uint32_t smem_to_u32(const void* p) {
    uint32_t a;
    asm("{ .reg .u64 t; cvta.to.shared.u64 t, %1; cvt.u32.u64 %0, t; }"
        : "=r"(a) : "l"(p));
    return a;
}

#define LDSM_X4(r0, r1, r2, r3, addr) \
    asm volatile("ldmatrix.sync.aligned.m8n8.x4.shared.b16 {%0,%1,%2,%3}, [%4];" \
                 : "=r"(r0), "=r"(r1), "=r"(r2), "=r"(r3) : "r"(addr))

#define LDSM_X4_T(r0, r1, r2, r3, addr) \
    asm volatile("ldmatrix.sync.aligned.m8n8.x4.trans.shared.b16 {%0,%1,%2,%3}, [%4];" \
                 : "=r"(r0), "=r"(r1), "=r"(r2), "=r"(r3) : "r"(addr))

#define MMA_BF16(d, a, b) \
    asm volatile("mma.sync.aligned.m16n8k16.row.col.f32.bf16.bf16.f32 " \
                 "{%0,%1,%2,%3}, {%4,%5,%6,%7}, {%8,%9}, {%0,%1,%2,%3};" \
                 : "+f"((d)[0]), "+f"((d)[1]), "+f"((d)[2]), "+f"((d)[3]) \
                 : "r"((a)[0]), "r"((a)[1]), "r"((a)[2]), "r"((a)[3]), \
                   "r"((b)[0]), "r"((b)[1]))

#define CP_ASYNC16(dst, src) \
    asm volatile("cp.async.cg.shared.global [%0], [%1], 16;" :: "r"(dst), "l"(src))
#define CP_COMMIT() asm volatile("cp.async.commit_group;")
#define CP_WAIT1()  asm volatile("cp.async.wait_group 1;" ::: "memory")

__device__ __forceinline__ uint32_t pack2bf(float a, float b) {
    __nv_bfloat162 t = __floats2bfloat162_rn(a, b);
    return *(uint32_t*)&t;
}

// ===========================================================================
// Split kernel: fp32 * mul -> bf16 hi + bf16 lo
// ===========================================================================
__global__ __launch_bounds__(256) void split_kernel(
    const float* __restrict__ src, __nv_bfloat16* __restrict__ h,
    __nv_bfloat16* __restrict__ l, int n4, float mul)
{
    int i = blockIdx.x * 256 + threadIdx.x;
    if (i >= n4) return;
    float4 v = *(const float4*)(src + (size_t)i * 4);
    v.x *= mul; v.y *= mul; v.z *= mul; v.w *= mul;
    __nv_bfloat16 h0 = __float2bfloat16(v.x), h1 = __float2bfloat16(v.y);
    __nv_bfloat16 h2 = __float2bfloat16(v.z), h3 = __float2bfloat16(v.w);
    __nv_bfloat162 hh0; hh0.x = h0; hh0.y = h1;
    __nv_bfloat162 hh1; hh1.x = h2; hh1.y = h3;
    __nv_bfloat162 ll0;
    ll0.x = __float2bfloat16(v.x - __bfloat162float(h0));
    ll0.y = __float2bfloat16(v.y - __bfloat162float(h1));
    __nv_bfloat162 ll1;
    ll1.x = __float2bfloat16(v.z - __bfloat162float(h2));
    ll1.y = __float2bfloat16(v.w - __bfloat162float(h3));
    *(__nv_bfloat162*)(h + (size_t)i * 4)     = hh0;
    *(__nv_bfloat162*)(h + (size_t)i * 4 + 2) = hh1;
    *(__nv_bfloat162*)(l + (size_t)i * 4)     = ll0;
    *(__nv_bfloat162*)(l + (size_t)i * 4 + 2) = ll1;
}

// ===========================================================================
// Pipelined mma.sync GEMM on preconverted bf16 hi/lo inputs.
// ===========================================================================
#define RSTRIDE 40
#define TILE_E  (128 * RSTRIDE)
#define STAGE_E (4 * TILE_E)
#define GEMM_SMEM_BYTES (2 * STAGE_E * 2)

__global__ __launch_bounds__(256, 2) void gemm_mma_kernel(
    const __nv_bfloat16* __restrict__ Ah, const __nv_bfloat16* __restrict__ Al,
    const __nv_bfloat16* __restrict__ Bh, const __nv_bfloat16* __restrict__ Bl,
    const float* __restrict__ bias, float biasmul,
    float* __restrict__ Cf, __nv_bfloat16* __restrict__ Ch,
    __nv_bfloat16* __restrict__ Cl,
    int M, int N, int K)
{
    extern __shared__ __nv_bfloat16 sm[];
    const int tid = threadIdx.x;
    const int lane = tid & 31;
    const int wid = tid >> 5;
    const int bm = blockIdx.y * 128;
    const int bn = blockIdx.x * 128;
    const int wm = (wid & 3) * 32;
    const int wn = (wid >> 2) * 64;
    const uint32_t sbase = smem_to_u32(sm);

    const __nv_bfloat16* srcs[4] = {
        Ah + (size_t)bm * K, Al + (size_t)bm * K,
        Bh + (size_t)bn * K, Bl + (size_t)bn * K };

    const int ld_row = tid >> 1;
    const int ld_ch0 = (tid & 1) * 2;

    float acc[2][8][4];
#pragma unroll
    for (int mi = 0; mi < 2; mi++)
#pragma unroll
        for (int nj = 0; nj < 8; nj++)
#pragma unroll
            for (int e = 0; e < 4; e++) acc[mi][nj][e] = 0.f;

    const int a_row_l = lane & 15;
    const int a_col_l = (lane >> 4) * 8;
    const int b_seg = lane >> 3;
    const int b_r8 = lane & 7;
    const int b_row_add = (b_seg >> 1) * 8;
    const int b_col_add = (b_seg & 1) * 8;

    const int nchunk = K >> 5;

#pragma unroll
    for (int t = 0; t < 4; t++) {
#pragma unroll
        for (int c = 0; c < 2; c++) {
            uint32_t sdst = sbase +
                (uint32_t)(t * TILE_E + ld_row * RSTRIDE + (ld_ch0 + c) * 8) * 2;
            const __nv_bfloat16* gsrc = srcs[t] + (size_t)ld_row * K + (ld_ch0 + c) * 8;
            CP_ASYNC16(sdst, gsrc);
        }
    }
    CP_COMMIT();

    for (int ck = 0; ck < nchunk; ck++) {
        if (ck + 1 < nchunk) {
            const uint32_t stoff = (uint32_t)(((ck + 1) & 1) * STAGE_E) * 2;
            const int k0n = (ck + 1) << 5;
#pragma unroll
            for (int t = 0; t < 4; t++) {
#pragma unroll
                for (int c = 0; c < 2; c++) {
                    uint32_t sdst = sbase + stoff +
                        (uint32_t)(t * TILE_E + ld_row * RSTRIDE + (ld_ch0 + c) * 8) * 2;
                    const __nv_bfloat16* gsrc =
                        srcs[t] + (size_t)ld_row * K + k0n + (ld_ch0 + c) * 8;
                    CP_ASYNC16(sdst, gsrc);
                }
            }
        }
        CP_COMMIT();
        CP_WAIT1();
        __syncthreads();

        const uint32_t st = sbase + (uint32_t)((ck & 1) * STAGE_E) * 2;
        const uint32_t sAH = st;
        const uint32_t sAL = st + (uint32_t)TILE_E * 2;
        const uint32_t sBH = st + (uint32_t)(2 * TILE_E) * 2;
        const uint32_t sBL = st + (uint32_t)(3 * TILE_E) * 2;

#pragma unroll
        for (int ks = 0; ks < 2; ks++) {
            const int kcol = ks * 16 + a_col_l;
            uint32_t ah[2][4], al[2][4];
#pragma unroll
            for (int mi = 0; mi < 2; mi++) {
                uint32_t eo = (uint32_t)((wm + mi * 16 + a_row_l) * RSTRIDE + kcol) * 2;
                LDSM_X4(ah[mi][0], ah[mi][1], ah[mi][2], ah[mi][3], sAH + eo);
                LDSM_X4(al[mi][0], al[mi][1], al[mi][2], al[mi][3], sAL + eo);
            }
#pragma unroll
            for (int g = 0; g < 4; g++) {
                uint32_t eo = (uint32_t)((wn + g * 16 + b_row_add + b_r8) * RSTRIDE +
                                         ks * 16 + b_col_add) * 2;
                uint32_t bh[4], bl[4];
                LDSM_X4(bh[0], bh[1], bh[2], bh[3], sBH + eo);
                LDSM_X4(bl[0], bl[1], bl[2], bl[3], sBL + eo);
#pragma unroll
                for (int half = 0; half < 2; half++) {
                    int nj = g * 2 + half;
                    uint32_t* bhp = bh + half * 2;
                    uint32_t* blp = bl + half * 2;
#pragma unroll
                    for (int mi = 0; mi < 2; mi++) {
                        MMA_BF16(acc[mi][nj], ah[mi], bhp);
                        MMA_BF16(acc[mi][nj], ah[mi], blp);
                        MMA_BF16(acc[mi][nj], al[mi], bhp);
                    }
                }
            }
        }
        __syncthreads();
    }

    const int er = lane >> 2;
    const int ec = (lane & 3) * 2;
#pragma unroll
    for (int mi = 0; mi < 2; mi++) {
#pragma unroll
        for (int nj = 0; nj < 8; nj++) {
            int m0 = bm + wm + mi * 16 + er;
            int n0 = bn + wn + nj * 8 + ec;
            float b0 = __ldg(bias + n0) * biasmul;
            float b1 = __ldg(bias + n0 + 1) * biasmul;
            float v00 = acc[mi][nj][0] + b0, v01 = acc[mi][nj][1] + b1;
            float v10 = acc[mi][nj][2] + b0, v11 = acc[mi][nj][3] + b1;
            if (Cf) {
                *(float2*)(Cf + (size_t)m0 * N + n0) = make_float2(v00, v01);
                *(float2*)(Cf + (size_t)(m0 + 8) * N + n0) = make_float2(v10, v11);
            } else {
                __nv_bfloat16 h00 = __float2bfloat16(v00);
                __nv_bfloat16 h01 = __float2bfloat16(v01);
                __nv_bfloat16 h10 = __float2bfloat16(v10);
                __nv_bfloat16 h11 = __float2bfloat16(v11);
                __nv_bfloat162 hv0; hv0.x = h00; hv0.y = h01;
                __nv_bfloat162 hv1; hv1.x = h10; hv1.y = h11;
                __nv_bfloat162 lv0;
                lv0.x = __float2bfloat16(v00 - __bfloat162float(h00));
                lv0.y = __float2bfloat16(v01 - __bfloat162float(h01));
                __nv_bfloat162 lv1;
                lv1.x = __float2bfloat16(v10 - __bfloat162float(h10));
                lv1.y = __float2bfloat16(v11 - __bfloat162float(h11));
                *(__nv_bfloat162*)(Ch + (size_t)m0 * N + n0) = hv0;
                *(__nv_bfloat162*)(Ch + (size_t)(m0 + 8) * N + n0) = hv1;
                *(__nv_bfloat162*)(Cl + (size_t)m0 * N + n0) = lv0;
                *(__nv_bfloat162*)(Cl + (size_t)(m0 + 8) * N + n0) = lv1;
            }
        }
    }
}

// ===========================================================================
// Tensor-core flash attention, causal, d=64, Q PRE-SCALED by 1/sqrt(d).
// Block = 128 q-rows (8 warps x m16), 64-col K/V tiles, 2-stage cp.async
// pipeline on K/V hi/lo. Output -> bf16 hi/lo.
// ===========================================================================
#define FSTRIDE 72
#define FKV_E   (64 * FSTRIDE)          // 4608 el per array
#define FSTAGE_E (4 * FKV_E)            // KH,KL,VH,VL
#define FLASH_SMEM_BYTES (2 * FSTAGE_E * 2)   // 73728

__device__ __forceinline__ void flash_ldkv(
    uint32_t sb, uint32_t stoff_bytes,
    const __nv_bfloat16* __restrict__ kvh, const __nv_bfloat16* __restrict__ kvl,
    size_t kvrow, int tid)
{
#pragma unroll
    for (int a = 0; a < 4; a++) {
        const __nv_bfloat16* base = (a & 1) ? kvl : kvh;
        const size_t add = (a >> 1) ? (size_t)C_ : 0;
#pragma unroll
        for (int hf = 0; hf < 2; hf++) {
            int c = tid + hf * 256;          // 0..511
            int row = c >> 3;
            int col = (c & 7) * 8;
            const __nv_bfloat16* src = base + kvrow + (size_t)row * (2 * C_) + add + col;
            uint32_t dst = sb + stoff_bytes +
                (uint32_t)(a * FKV_E + row * FSTRIDE + col) * 2;
            CP_ASYNC16(dst, src);
        }
    }
}

__global__ __launch_bounds__(256) void flash_mma_kernel(
    const __nv_bfloat16* __restrict__ qh, const __nv_bfloat16* __restrict__ ql,
    const __nv_bfloat16* __restrict__ kvh, const __nv_bfloat16* __restrict__ kvl,
    __nv_bfloat16* __restrict__ oh, __nv_bfloat16* __restrict__ ol)
{
    extern __shared__ __nv_bfloat16 fsm[];
    const uint32_t sb = smem_to_u32(fsm);

    const int qt = blockIdx.x;            // 0..7  (128-row tiles)
    const int h  = blockIdx.y;
    const int b  = blockIdx.z;
    const int tid = threadIdx.x;
    const int lane = tid & 31;
    const int wid = tid >> 5;              // 0..7
    const int wm = wid * 16;

    const int fr = lane >> 2;
    const int fc = (lane & 3) * 2;

    // Q fragments (hi/lo) — Q is pre-scaled by 1/sqrt(d)
    uint32_t qfh[4][4], qfl[4][4];
    {
        const size_t qrow0 = (size_t)(b * T_ + qt * 128 + wm + fr) * C_ + h * D_;
        const size_t qrow8 = qrow0 + (size_t)8 * C_;
#pragma unroll
        for (int ks = 0; ks < 4; ks++) {
            int c0 = ks * 16 + fc;
            qfh[ks][0] = *(const uint32_t*)(qh + qrow0 + c0);
            qfh[ks][1] = *(const uint32_t*)(qh + qrow8 + c0);
            qfh[ks][2] = *(const uint32_t*)(qh + qrow0 + c0 + 8);
            qfh[ks][3] = *(const uint32_t*)(qh + qrow8 + c0 + 8);
            qfl[ks][0] = *(const uint32_t*)(ql + qrow0 + c0);
            qfl[ks][1] = *(const uint32_t*)(ql + qrow8 + c0);
            qfl[ks][2] = *(const uint32_t*)(ql + qrow0 + c0 + 8);
            qfl[ks][3] = *(const uint32_t*)(ql + qrow8 + c0 + 8);
        }
    }

    float mrow0 = -1e30f, mrow1 = -1e30f, lrow0 = 0.f, lrow1 = 0.f;
    float oacc[8][4];
#pragma unroll
    for (int j = 0; j < 8; j++)
#pragma unroll
        for (int e = 0; e < 4; e++) oacc[j][e] = 0.f;

    const int b_seg = lane >> 3;
    const int b_r8 = lane & 7;
    const int b_row_add = (b_seg >> 1) * 8;
    const int b_col_add = (b_seg & 1) * 8;
    const int v_row_l = lane & 15;
    const int v_col_l = (lane >> 4) * 8;

    const int row_g0 = qt * 128 + wm + fr;
    const int row_g1 = row_g0 + 8;
    const int st_max = 2 * qt + 1;

    // prologue: stage 0 loads
    flash_ldkv(sb, 0, kvh, kvl,
               (size_t)(b * S_) * (2 * C_) + h * D_, tid);
    CP_COMMIT();

    for (int st = 0; st <= st_max; st++) {
        __syncthreads();   // all warps done reading stage (st+1)&1 (from st-1)
        if (st + 1 <= st_max) {
            flash_ldkv(sb, (uint32_t)(((st + 1) & 1) * FSTAGE_E) * 2, kvh, kvl,
                       (size_t)(b * S_ + (st + 1) * 64) * (2 * C_) + h * D_, tid);
        }
        CP_COMMIT();
        CP_WAIT1();
        __syncthreads();   // stage st&1 visible to all

        const uint32_t stb = sb + (uint32_t)((st & 1) * FSTAGE_E) * 2;
        const uint32_t skh_b = stb;
        const uint32_t skl_b = stb + (uint32_t)FKV_E * 2;
        const uint32_t svh_b = stb + (uint32_t)(2 * FKV_E) * 2;
        const uint32_t svl_b = stb + (uint32_t)(3 * FKV_E) * 2;

        // warp fully masked? (all rows < col_min)
        const bool active = (qt * 128 + wm + 15) >= st * 64;
        if (!active) continue;

        // ---- S = Q K^T ----
        float sacc[8][4];
#pragma unroll
        for (int j = 0; j < 8; j++)
#pragma unroll
            for (int e = 0; e < 4; e++) sacc[j][e] = 0.f;

#pragma unroll
        for (int ks = 0; ks < 4; ks++) {
#pragma unroll
            for (int g = 0; g < 4; g++) {
                uint32_t eo = (uint32_t)((g * 16 + b_row_add + b_r8) * FSTRIDE +
                                         ks * 16 + b_col_add) * 2;
                uint32_t bh[4], bl[4];
                LDSM_X4(bh[0], bh[1], bh[2], bh[3], skh_b + eo);
                LDSM_X4(bl[0], bl[1], bl[2], bl[3], skl_b + eo);
#pragma unroll
                for (int half = 0; half < 2; half++) {
                    int nj = g * 2 + half;
                    uint32_t* bhp = bh + half * 2;
                    uint32_t* blp = bl + half * 2;
                    MMA_BF16(sacc[nj], qfh[ks], bhp);
                    MMA_BF16(sacc[nj], qfh[ks], blp);
                    MMA_BF16(sacc[nj], qfl[ks], bhp);
                }
            }
        }

        // ---- causal mask (boundary tiles only) ----
        if (st >= 2 * qt) {
#pragma unroll
            for (int nj = 0; nj < 8; nj++) {
#pragma unroll
                for (int e = 0; e < 4; e++) {
                    int col = st * 64 + nj * 8 + fc + (e & 1);
                    int row = (e < 2) ? row_g0 : row_g1;
                    if (col > row) sacc[nj][e] = -1e30f;
                }
            }
        }

        // ---- online softmax ----
        float mx0 = -1e30f, mx1 = -1e30f;
#pragma unroll
        for (int nj = 0; nj < 8; nj++) {
            mx0 = fmaxf(mx0, fmaxf(sacc[nj][0], sacc[nj][1]));
            mx1 = fmaxf(mx1, fmaxf(sacc[nj][2], sacc[nj][3]));
        }
        mx0 = fmaxf(mx0, __shfl_xor_sync(0xffffffffu, mx0, 1));
        mx0 = fmaxf(mx0, __shfl_xor_sync(0xffffffffu, mx0, 2));
        mx1 = fmaxf(mx1, __shfl_xor_sync(0xffffffffu, mx1, 1));
        mx1 = fmaxf(mx1, __shfl_xor_sync(0xffffffffu, mx1, 2));

        float mn0 = fmaxf(mrow0, mx0);
        float mn1 = fmaxf(mrow1, mx1);
        float c0 = __expf(mrow0 - mn0);
        float c1 = __expf(mrow1 - mn1);
        mrow0 = mn0; mrow1 = mn1;

        float rs0 = 0.f, rs1 = 0.f;
        uint32_t pfh[4][4], pfl[4][4];
#pragma unroll
        for (int kp = 0; kp < 4; kp++) {
            float p[2][4];
#pragma unroll
            for (int s2 = 0; s2 < 2; s2++) {
                int nj = kp * 2 + s2;
                p[s2][0] = __expf(sacc[nj][0] - mn0);
                p[s2][1] = __expf(sacc[nj][1] - mn0);
                p[s2][2] = __expf(sacc[nj][2] - mn1);
                p[s2][3] = __expf(sacc[nj][3] - mn1);
                rs0 += p[s2][0] + p[s2][1];
                rs1 += p[s2][2] + p[s2][3];
            }
#pragma unroll
            for (int s2 = 0; s2 < 2; s2++) {
                float h00 = __bfloat162float(__float2bfloat16(p[s2][0]));
                float h01 = __bfloat162float(__float2bfloat16(p[s2][1]));
                float h10 = __bfloat162float(__float2bfloat16(p[s2][2]));
                float h11 = __bfloat162float(__float2bfloat16(p[s2][3]));
                pfh[kp][0 + s2 * 2] = pack2bf(h00, h01);
                pfh[kp][1 + s2 * 2] = pack2bf(h10, h11);
                pfl[kp][0 + s2 * 2] = pack2bf(p[s2][0] - h00, p[s2][1] - h01);
                pfl[kp][1 + s2 * 2] = pack2bf(p[s2][2] - h10, p[s2][3] - h11);
            }
        }
        rs0 += __shfl_xor_sync(0xffffffffu, rs0, 1);
        rs0 += __shfl_xor_sync(0xffffffffu, rs0, 2);
        rs1 += __shfl_xor_sync(0xffffffffu, rs1, 1);
        rs1 += __shfl_xor_sync(0xffffffffu, rs1, 2);
        lrow0 = lrow0 * c0 + rs0;
        lrow1 = lrow1 * c1 + rs1;

#pragma unroll
        for (int j = 0; j < 8; j++) {
            oacc[j][0] *= c0; oacc[j][1] *= c0;
            oacc[j][2] *= c1; oacc[j][3] *= c1;
        }

        // ---- O += P V ----
#pragma unroll
        for (int kp = 0; kp < 4; kp++) {
#pragma unroll
            for (int g = 0; g < 4; g++) {
                uint32_t eo = (uint32_t)((kp * 16 + v_row_l) * FSTRIDE +
                                         g * 16 + v_col_l) * 2;
                uint32_t vh[4], vl[4];
                LDSM_X4_T(vh[0], vh[1], vh[2], vh[3], svh_b + eo);
                LDSM_X4_T(vl[0], vl[1], vl[2], vl[3], svl_b + eo);
#pragma unroll
                for (int half = 0; half < 2; half++) {
                    int njd = g * 2 + half;
                    uint32_t* vhp = vh + half * 2;
                    uint32_t* vlp = vl + half * 2;
                    MMA_BF16(oacc[njd], pfh[kp], vhp);
                    MMA_BF16(oacc[njd], pfh[kp], vlp);
                    MMA_BF16(oacc[njd], pfl[kp], vhp);
                }
            }
        }
    }

    // ---- finalize ----
    const float inv0 = 1.f / lrow0;
    const float inv1 = 1.f / lrow1;
    const size_t orow0 = (size_t)(b * T_ + row_g0) * C_ + h * D_;
    const size_t orow8 = orow0 + (size_t)8 * C_;
#pragma unroll
    for (int njd = 0; njd < 8; njd++) {
        int col = njd * 8 + fc;
        float v00 = oacc[njd][0] * inv0, v01 = oacc[njd][1] * inv0;
        float v10 = oacc[njd][2] * inv1, v11 = oacc[njd][3] * inv1;
        __nv_bfloat16 h00 = __float2bfloat16(v00), h01 = __float2bfloat16(v01);
        __nv_bfloat16 h10 = __float2bfloat16(v10), h11 = __float2bfloat16(v11);
        __nv_bfloat162 hv0; hv0.x = h00; hv0.y = h01;
        __nv_bfloat162 hv1; hv1.x = h10; hv1.y = h11;
        __nv_bfloat162 lv0;
        lv0.x = __float2bfloat16(v00 - __bfloat162float(h00));
        lv0.y = __float2bfloat16(v01 - __bfloat162float(h01));
        __nv_bfloat162 lv1;
        lv1.x = __float2bfloat16(v10 - __bfloat162float(h10));
        lv1.y = __float2bfloat16(v11 - __bfloat162float(h11));
        *(__nv_bfloat162*)(oh + orow0 + col) = hv0;
        *(__nv_bfloat162*)(oh + orow8 + col) = hv1;
        *(__nv_bfloat162*)(ol + orow0 + col) = lv0;
        *(__nv_bfloat162*)(ol + orow8 + col) = lv1;
    }
}

// ---------------------------------------------------------------------------
// Launch
// ---------------------------------------------------------------------------
extern "C" void kernel_launch(void* const* d_in, const int* in_sizes, int n_in,
                              void* d_out, int out_size)
{
    const float* x       = (const float*)d_in[0];
    const float* feature = (const float*)d_in[1];
    const float* Wc      = (const float*)d_in[2];
    const float* bc      = (const float*)d_in[3];
    const float* Wf      = (const float*)d_in[4];
    const float* bf      = (const float*)d_in[5];
    const float* Wp      = (const float*)d_in[6];
    const float* bp      = (const float*)d_in[7];
    float* out           = (float*)d_out;

    __nv_bfloat16 *xh, *xl, *fh, *fl, *Wch, *Wcl, *Wfh, *Wfl, *Wph, *Wpl;
    __nv_bfloat16 *qh, *ql, *kvh, *kvl, *ah, *al;
    cudaGetSymbolAddress((void**)&xh, g_xh);   cudaGetSymbolAddress((void**)&xl, g_xl);
    cudaGetSymbolAddress((void**)&fh, g_fh);   cudaGetSymbolAddress((void**)&fl, g_fl);
    cudaGetSymbolAddress((void**)&Wch, g_Wch); cudaGetSymbolAddress((void**)&Wcl, g_Wcl);
    cudaGetSymbolAddress((void**)&Wfh, g_Wfh); cudaGetSymbolAddress((void**)&Wfl, g_Wfl);
    cudaGetSymbolAddress((void**)&Wph, g_Wph); cudaGetSymbolAddress((void**)&Wpl, g_Wpl);
    cudaGetSymbolAddress((void**)&qh, g_qh);   cudaGetSymbolAddress((void**)&ql, g_ql);
    cudaGetSymbolAddress((void**)&kvh, g_kvh); cudaGetSymbolAddress((void**)&kvl, g_kvl);
    cudaGetSymbolAddress((void**)&ah, g_ah);   cudaGetSymbolAddress((void**)&al, g_al);

    cudaFuncSetAttribute(gemm_mma_kernel,
                         cudaFuncAttributeMaxDynamicSharedMemorySize, GEMM_SMEM_BYTES);
    cudaFuncSetAttribute(flash_mma_kernel,
                         cudaFuncAttributeMaxDynamicSharedMemorySize, FLASH_SMEM_BYTES);

    // ---- 0) split fp32 inputs to bf16 hi/lo (Wc pre-scaled by 1/sqrt(d)) ----
    {
        int n4;
        n4 = (int)(NX / 4);
        split_kernel<<<(n4 + 255) / 256, 256>>>(x, xh, xl, n4, 1.f);
        split_kernel<<<(n4 + 255) / 256, 256>>>(feature, fh, fl, n4, 1.f);
        n4 = C_ * C_ / 4;
        split_kernel<<<(n4 + 255) / 256, 256>>>(Wc, Wch, Wcl, n4, 0.125f);
        split_kernel<<<(n4 + 255) / 256, 256>>>(Wp, Wph, Wpl, n4, 1.f);
        n4 = 2 * C_ * C_ / 4;
        split_kernel<<<(n4 + 255) / 256, 256>>>(Wf, Wfh, Wfl, n4, 1.f);
    }

    // ---- 1) q = x @ (Wc/8)^T + bc/8  -> bf16 hi/lo (pre-scaled) ----
    {
        dim3 grid(C_ / 128, (B_ * T_) / 128);
        gemm_mma_kernel<<<grid, 256, GEMM_SMEM_BYTES>>>(
            xh, xl, Wch, Wcl, bc, 0.125f, nullptr, qh, ql, B_ * T_, C_, C_);
    }
    // ---- 2) kv = feature @ Wf^T + bf -> bf16 hi/lo ----
    {
        dim3 grid((2 * C_) / 128, (B_ * S_) / 128);
        gemm_mma_kernel<<<grid, 256, GEMM_SMEM_BYTES>>>(
            fh, fl, Wfh, Wfl, bf, 1.f, nullptr, kvh, kvl, B_ * S_, 2 * C_, C_);
    }
    // ---- 3) flash attention (causal, 128-row blocks, pipelined K/V) ----
    {
        dim3 grid(T_ / 128, H_, B_);
        flash_mma_kernel<<<grid, 256, FLASH_SMEM_BYTES>>>(qh, ql, kvh, kvl, ah, al);
    }
    // ---- 4) out = attn @ Wp^T + bp -> fp32 ----
    {
        dim3 grid(C_ / 128, (B_ * T_) / 128);
        gemm_mma_kernel<<<grid, 256, GEMM_SMEM_BYTES>>>(
            ah, al, Wph, Wpl, bp, 1.f, out, nullptr, nullptr, B_ * T_, C_, C_);
    }
}